// round 4
// baseline (speedup 1.0000x reference)
#include <cuda_runtime.h>
#include <cuda_bf16.h>
#include <cstdint>

#define NB   4
#define TQ   2048
#define NE   1024
#define HD   128
#define TKF  4096
#define NM   16384

// ---------------- device scratch (no allocations allowed) ----------------
__device__ float g_q [(size_t)NB * TQ  * HD];   // projected queries   4 MB
__device__ float g_kf[(size_t)NB * TKF * HD];   // prefix-k ++ k       8 MB
__device__ float g_vf[(size_t)NB * TKF * HD];   // prefix-v ++ v       8 MB

// =========================================================================
// 1) prefix copy: ki/vi[:, :, s:s+128] -> g_kf/g_vf[:, 0:2048, :]
// =========================================================================
__global__ __launch_bounds__(256) void copy_prefix_kernel(
    const float* __restrict__ ki, const float* __restrict__ vi,
    const int* __restrict__ idxp)
{
    const int s  = idxp[0] * HD;
    const int e4 = blockIdx.x * 256 + threadIdx.x;   // float4 units, 262144 total
    const int d4 = e4 & 31;
    const int t  = (e4 >> 5) & (TQ - 1);
    const int b  = e4 >> 16;
    const size_t src = ((size_t)b * TQ + t) * NE + s + (size_t)d4 * 4;
    const size_t dst = ((size_t)b * TKF + t) * HD + (size_t)d4 * 4;
    *(float4*)(g_kf + dst) = *(const float4*)(ki + src);
    *(float4*)(g_vf + dst) = *(const float4*)(vi + src);
}

// =========================================================================
// 2) projection GEMM: [8192,1024] x [1024,128] + bias
//    mode 0 -> g_q (plain rows), mode 1 -> g_kf rows 2048.., mode 2 -> g_vf
// =========================================================================
__global__ __launch_bounds__(256) void proj_kernel(
    const float* __restrict__ X, const float* __restrict__ W,
    const float* __restrict__ bias, int mode)
{
    __shared__ float As[64][17];
    __shared__ float Bs[16][128];
    const int t   = threadIdx.x;
    const int bm0 = blockIdx.x * 64;
    const int tr  = t >> 4;           // 0..15 -> rows tr*4..+3
    const int tc  = t & 15;           // 0..15 -> cols tc*8..+7
    float acc[4][8];
    #pragma unroll
    for (int i = 0; i < 4; i++)
        #pragma unroll
        for (int j = 0; j < 8; j++) acc[i][j] = 0.f;

    const int ar = t >> 2, ac = (t & 3) * 4;
    const int br = t >> 5, bc = (t & 31) * 4;

    for (int k0 = 0; k0 < NE; k0 += 16) {
        float4 av = *(const float4*)(X + (size_t)(bm0 + ar) * NE + k0 + ac);
        As[ar][ac + 0] = av.x; As[ar][ac + 1] = av.y;
        As[ar][ac + 2] = av.z; As[ar][ac + 3] = av.w;
        *(float4*)(&Bs[br][bc])     = *(const float4*)(W + (size_t)(k0 + br) * HD + bc);
        *(float4*)(&Bs[br + 8][bc]) = *(const float4*)(W + (size_t)(k0 + br + 8) * HD + bc);
        __syncthreads();
        #pragma unroll
        for (int kk = 0; kk < 16; kk++) {
            float a[4];
            #pragma unroll
            for (int i = 0; i < 4; i++) a[i] = As[tr * 4 + i][kk];
            float4 b0 = *(const float4*)(&Bs[kk][tc * 8]);
            float4 b1 = *(const float4*)(&Bs[kk][tc * 8 + 4]);
            float bb[8] = {b0.x, b0.y, b0.z, b0.w, b1.x, b1.y, b1.z, b1.w};
            #pragma unroll
            for (int i = 0; i < 4; i++)
                #pragma unroll
                for (int j = 0; j < 8; j++)
                    acc[i][j] = fmaf(a[i], bb[j], acc[i][j]);
        }
        __syncthreads();
    }

    float* dst = (mode == 0) ? g_q : (mode == 1) ? g_kf : g_vf;
    float4 bb0 = *(const float4*)(bias + tc * 8);
    float4 bb1 = *(const float4*)(bias + tc * 8 + 4);
    #pragma unroll
    for (int i = 0; i < 4; i++) {
        int row = bm0 + tr * 4 + i;
        int bi  = row >> 11;
        int tt  = row & (TQ - 1);
        size_t orow = (mode == 0) ? (size_t)row : ((size_t)bi * TKF + TQ + tt);
        float4 o0 = make_float4(acc[i][0] + bb0.x, acc[i][1] + bb0.y,
                                acc[i][2] + bb0.z, acc[i][3] + bb0.w);
        float4 o1 = make_float4(acc[i][4] + bb1.x, acc[i][5] + bb1.y,
                                acc[i][6] + bb1.z, acc[i][7] + bb1.w);
        *(float4*)(dst + orow * HD + tc * 8)     = o0;
        *(float4*)(dst + orow * HD + tc * 8 + 4) = o1;
    }
}

// =========================================================================
// 3) causal flash attention, 64 queries/CTA, 64-key tiles, writes gate*out
// =========================================================================
#define ATTN_SMEM (3 * 64 * 32 * 16 + 64 * 68 * 4)

__global__ __launch_bounds__(256) void attn_kernel(
    const float* __restrict__ gate, float* __restrict__ out)
{
    extern __shared__ float smem_dyn[];
    float4* Qs = (float4*)smem_dyn;          // 64 rows x 32 float4 (swizzled)
    float4* Ks = Qs + 64 * 32;
    float4* Vs = Ks + 64 * 32;
    float*  Ss = (float*)(Vs + 64 * 32);     // 64 x 68

    const int t  = threadIdx.x;
    const int b  = blockIdx.y;
    const int qb = blockIdx.x;               // 0..31
    const int tq = t >> 4;                   // rows 4tq..+3
    const int tk = t & 15;                   // score cols 4tk..+3 ; dims 4tk / 64+4tk
    const float scale = 0.08838834764831845f;   // 1/sqrt(128)

    const float4* qsrc = (const float4*)(g_q + ((size_t)(b * TQ + qb * 64)) * HD);
    #pragma unroll
    for (int i = 0; i < 8; i++) {
        int idx = t + i * 256; int r = idx >> 5, c = idx & 31;
        Qs[r * 32 + (c ^ ((r >> 2) & 7))] = qsrc[idx];
    }

    float m[4], l[4], acc[4][8];
    #pragma unroll
    for (int i = 0; i < 4; i++) {
        m[i] = -1e30f; l[i] = 0.f;
        #pragma unroll
        for (int j = 0; j < 8; j++) acc[i][j] = 0.f;
    }

    const int ntiles = qb + 33;
    for (int tile = 0; tile < ntiles; tile++) {
        __syncthreads();
        const float4* ksrc = (const float4*)(g_kf + ((size_t)(b * TKF + tile * 64)) * HD);
        const float4* vsrc = (const float4*)(g_vf + ((size_t)(b * TKF + tile * 64)) * HD);
        #pragma unroll
        for (int i = 0; i < 8; i++) {
            int idx = t + i * 256; int r = idx >> 5, c = idx & 31;
            int sw = r * 32 + (c ^ ((r >> 2) & 7));
            Ks[sw] = ksrc[idx];
            Vs[sw] = vsrc[idx];
        }
        __syncthreads();

        float s[4][4];
        #pragma unroll
        for (int i = 0; i < 4; i++)
            #pragma unroll
            for (int j = 0; j < 4; j++) s[i][j] = 0.f;

        #pragma unroll 4
        for (int c = 0; c < 32; c++) {
            float4 a[4], kv[4];
            #pragma unroll
            for (int i = 0; i < 4; i++) a[i]  = Qs[(4 * tq + i) * 32 + (c ^ (tq & 7))];
            #pragma unroll
            for (int j = 0; j < 4; j++) kv[j] = Ks[(4 * tk + j) * 32 + (c ^ (tk & 7))];
            #pragma unroll
            for (int i = 0; i < 4; i++)
                #pragma unroll
                for (int j = 0; j < 4; j++)
                    s[i][j] = fmaf(a[i].w, kv[j].w, fmaf(a[i].z, kv[j].z,
                              fmaf(a[i].y, kv[j].y, fmaf(a[i].x, kv[j].x, s[i][j]))));
        }

        const bool lastTile = (tile == ntiles - 1);
        #pragma unroll
        for (int i = 0; i < 4; i++)
            #pragma unroll
            for (int j = 0; j < 4; j++) {
                s[i][j] *= scale;
                if (lastTile && (4 * tk + j > 4 * tq + i)) s[i][j] = -1e30f;
            }

        // row max over 16-lane tk group
        float tmax[4];
        #pragma unroll
        for (int i = 0; i < 4; i++)
            tmax[i] = fmaxf(fmaxf(s[i][0], s[i][1]), fmaxf(s[i][2], s[i][3]));
        #pragma unroll
        for (int o = 1; o < 16; o <<= 1)
            #pragma unroll
            for (int i = 0; i < 4; i++)
                tmax[i] = fmaxf(tmax[i], __shfl_xor_sync(0xffffffffu, tmax[i], o));

        float corr[4], rs[4];
        #pragma unroll
        for (int i = 0; i < 4; i++) {
            float mn = fmaxf(m[i], tmax[i]);
            corr[i] = __expf(m[i] - mn);
            m[i] = mn;
            rs[i] = 0.f;
            #pragma unroll
            for (int j = 0; j < 4; j++) {
                s[i][j] = __expf(s[i][j] - mn);
                rs[i] += s[i][j];
            }
        }
        #pragma unroll
        for (int o = 1; o < 16; o <<= 1)
            #pragma unroll
            for (int i = 0; i < 4; i++)
                rs[i] += __shfl_xor_sync(0xffffffffu, rs[i], o);
        #pragma unroll
        for (int i = 0; i < 4; i++) {
            l[i] = l[i] * corr[i] + rs[i];
            #pragma unroll
            for (int j = 0; j < 8; j++) acc[i][j] *= corr[i];
            *(float4*)&Ss[(4 * tq + i) * 68 + 4 * tk] =
                make_float4(s[i][0], s[i][1], s[i][2], s[i][3]);
        }
        __syncthreads();

        // P @ V
        #pragma unroll 2
        for (int jj = 0; jj < 16; jj++) {
            float4 p[4];
            #pragma unroll
            for (int i = 0; i < 4; i++)
                p[i] = *(const float4*)&Ss[(4 * tq + i) * 68 + jj * 4];
            #pragma unroll
            for (int e = 0; e < 4; e++) {
                int j = jj * 4 + e;
                int key = (j >> 2) & 7;
                float4 v0 = Vs[j * 32 + (tk ^ key)];
                float4 v1 = Vs[j * 32 + ((16 + tk) ^ key)];
                #pragma unroll
                for (int i = 0; i < 4; i++) {
                    float pv = (e == 0) ? p[i].x : (e == 1) ? p[i].y : (e == 2) ? p[i].z : p[i].w;
                    acc[i][0] = fmaf(pv, v0.x, acc[i][0]);
                    acc[i][1] = fmaf(pv, v0.y, acc[i][1]);
                    acc[i][2] = fmaf(pv, v0.z, acc[i][2]);
                    acc[i][3] = fmaf(pv, v0.w, acc[i][3]);
                    acc[i][4] = fmaf(pv, v1.x, acc[i][4]);
                    acc[i][5] = fmaf(pv, v1.y, acc[i][5]);
                    acc[i][6] = fmaf(pv, v1.z, acc[i][6]);
                    acc[i][7] = fmaf(pv, v1.w, acc[i][7]);
                }
            }
        }
    }

    const float gv = gate[0];
    #pragma unroll
    for (int i = 0; i < 4; i++) {
        float inv = gv / l[i];
        size_t row = (size_t)(b * TQ + qb * 64 + 4 * tq + i) * HD;
        float4 o0 = make_float4(acc[i][0] * inv, acc[i][1] * inv,
                                acc[i][2] * inv, acc[i][3] * inv);
        float4 o1 = make_float4(acc[i][4] * inv, acc[i][5] * inv,
                                acc[i][6] * inv, acc[i][7] * inv);
        *(float4*)(out + row + 4 * tk)      = o0;
        *(float4*)(out + row + 64 + 4 * tk) = o1;
    }
}

// =========================================================================
// 4) kNN memory attention: exact top-32 over 16384 keys, softmax, gather,
//    adds (1-gate)*mem_out into d_out
// =========================================================================
__global__ __launch_bounds__(256) void mem_kernel(
    const float* __restrict__ mem_keys, const float* __restrict__ mem_vals,
    const float* __restrict__ gate, float* __restrict__ out)
{
    __shared__ float4 Qs[32 * 32];   // 32 queries x 128 dims
    __shared__ float4 Ks[64 * 32];   // 64 keys x 128 dims

    const int t  = threadIdx.x;
    const int b  = blockIdx.y;
    const int q0 = blockIdx.x * 32;
    const int mq = t >> 3;           // query within block (0..31)
    const int g  = t & 7;            // 8-lane group within query

    const float4* qsrc = (const float4*)(g_q + ((size_t)(b * TQ + q0)) * HD);
    #pragma unroll
    for (int i = 0; i < 4; i++) {
        int idx = t + i * 256; int r = idx >> 5, c = idx & 31;
        Qs[r * 32 + (c ^ (r & 7))] = qsrc[idx];
    }

    float lv[32]; int li[32];
    #pragma unroll
    for (int i = 0; i < 32; i++) { lv[i] = -1e30f; li[i] = 0; }
    float vmin = -1e30f; int amin = 0;

    const float4* kb = (const float4*)(mem_keys + (size_t)b * NM * HD);

    for (int tile = 0; tile < NM / 64; tile++) {
        __syncthreads();
        #pragma unroll
        for (int i = 0; i < 8; i++) {
            int idx = t + i * 256; int r = idx >> 5, c = idx & 31;
            Ks[r * 32 + (c ^ ((r >> 3) & 7))] = kb[(size_t)tile * 2048 + idx];
        }
        __syncthreads();

        float s[8];
        #pragma unroll
        for (int j = 0; j < 8; j++) s[j] = 0.f;
        #pragma unroll 4
        for (int c = 0; c < 32; c++) {
            float4 a = Qs[mq * 32 + (c ^ (mq & 7))];
            #pragma unroll
            for (int j = 0; j < 8; j++) {
                float4 kv = Ks[(8 * g + j) * 32 + (c ^ g)];
                s[j] = fmaf(a.w, kv.w, fmaf(a.z, kv.z,
                       fmaf(a.y, kv.y, fmaf(a.x, kv.x, s[j]))));
            }
        }

        #pragma unroll
        for (int j = 0; j < 8; j++) {
            if (s[j] > vmin) {
                lv[amin] = s[j]; li[amin] = tile * 64 + 8 * g + j;
                vmin = lv[0]; amin = 0;
                #pragma unroll 8
                for (int p = 1; p < 32; p++)
                    if (lv[p] < vmin) { vmin = lv[p]; amin = p; }
            }
        }
    }

    // sort local list descending
    for (int a = 1; a < 32; a++) {
        float v = lv[a]; int ii = li[a]; int p = a - 1;
        while (p >= 0 && lv[p] < v) { lv[p + 1] = lv[p]; li[p + 1] = li[p]; p--; }
        lv[p + 1] = v; li[p + 1] = ii;
    }

    // 8-lane tournament merge of top-32, fused softmax + gather
    const int lane = t & 31;
    const float* vb = mem_vals + (size_t)b * NM * HD;
    float accv[16];
    #pragma unroll
    for (int u = 0; u < 16; u++) accv[u] = 0.f;
    float sumw = 0.f, vmax = 0.f;
    int ptr = 0;

    for (int it = 0; it < 32; it++) {
        float bv = (ptr < 32) ? lv[ptr] : -1e30f;
        int   wl = lane;
        #pragma unroll
        for (int o = 1; o < 8; o <<= 1) {
            float ov = __shfl_xor_sync(0xffffffffu, bv, o);
            int   ol = __shfl_xor_sync(0xffffffffu, wl, o);
            if (ov > bv) { bv = ov; wl = ol; }
        }
        int myi  = li[ptr < 32 ? ptr : 31];
        int widx = __shfl_sync(0xffffffffu, myi, wl);
        if (lane == wl) ptr++;
        if (it == 0) vmax = bv;
        float w = __expf((bv - vmax) * 0.03125f);   // /sqrt(1024)
        sumw += w;
        const float4* vrow = (const float4*)(vb + (size_t)widx * HD) + g * 4;
        #pragma unroll
        for (int u = 0; u < 4; u++) {
            float4 vv = vrow[u];
            accv[4 * u + 0] = fmaf(w, vv.x, accv[4 * u + 0]);
            accv[4 * u + 1] = fmaf(w, vv.y, accv[4 * u + 1]);
            accv[4 * u + 2] = fmaf(w, vv.z, accv[4 * u + 2]);
            accv[4 * u + 3] = fmaf(w, vv.w, accv[4 * u + 3]);
        }
    }

    const float sc = (1.0f - gate[0]) / sumw;
    float* orow = out + ((size_t)(b * TQ + q0 + mq)) * HD + g * 16;
    #pragma unroll
    for (int u = 0; u < 4; u++) {
        float4 o = ((float4*)orow)[u];
        o.x += sc * accv[4 * u + 0];
        o.y += sc * accv[4 * u + 1];
        o.z += sc * accv[4 * u + 2];
        o.w += sc * accv[4 * u + 3];
        ((float4*)orow)[u] = o;
    }
}

// =========================================================================
extern "C" void kernel_launch(void* const* d_in, const int* in_sizes, int n_in,
                              void* d_out, int out_size) {
    const float* x        = (const float*)d_in[0];
    const float* ki       = (const float*)d_in[1];
    const float* vi       = (const float*)d_in[2];
    const float* mem_keys = (const float*)d_in[3];
    const float* mem_vals = (const float*)d_in[4];
    const float* Wq       = (const float*)d_in[5];
    const float* bq       = (const float*)d_in[6];
    const float* Wk       = (const float*)d_in[7];
    const float* bk       = (const float*)d_in[8];
    const float* Wv       = (const float*)d_in[9];
    const float* bv       = (const float*)d_in[10];
    const float* gate     = (const float*)d_in[11];
    const int*   idxp     = (const int*)d_in[12];
    float* out = (float*)d_out;

    cudaFuncSetAttribute(attn_kernel, cudaFuncAttributeMaxDynamicSharedMemorySize,
                         ATTN_SMEM);

    copy_prefix_kernel<<<1024, 256>>>(ki, vi, idxp);
    proj_kernel<<<128, 256>>>(x, Wq, bq, 0);
    proj_kernel<<<128, 256>>>(x, Wk, bk, 1);
    proj_kernel<<<128, 256>>>(x, Wv, bv, 2);
    attn_kernel<<<dim3(32, 4), 256, ATTN_SMEM>>>(gate, out);
    mem_kernel<<<dim3(64, 4), 256>>>(mem_keys, mem_vals, gate, out);
}

// round 6
// speedup vs baseline: 1.0275x; 1.0275x over previous
#include <cuda_runtime.h>
#include <cstdint>

#define NB   4
#define TQ   2048
#define NE   1024
#define HD   128
#define TKF  4096
#define NM   16384

typedef unsigned long long ull;

// ---------------- packed f32x2 helpers (sm_103a only) ----------------
__device__ __forceinline__ ull dup2(float x) {
    ull r; asm("mov.b64 %0, {%1, %1};" : "=l"(r) : "f"(x)); return r;
}
__device__ __forceinline__ float2 u2f(ull v) {
    float2 r; asm("mov.b64 {%0, %1}, %2;" : "=f"(r.x), "=f"(r.y) : "l"(v)); return r;
}
__device__ __forceinline__ ull ffma2(ull a, ull b, ull c) {
    ull d; asm("fma.rn.f32x2 %0, %1, %2, %3;" : "=l"(d) : "l"(a), "l"(b), "l"(c)); return d;
}
__device__ __forceinline__ ull fmul2(ull a, ull b) {
    ull d; asm("mul.rn.f32x2 %0, %1, %2;" : "=l"(d) : "l"(a), "l"(b)); return d;
}

// ---------------- device scratch ----------------
__device__ float g_q [(size_t)NB * TQ  * HD];
__device__ float g_kf[(size_t)NB * TKF * HD];
__device__ float g_vf[(size_t)NB * TKF * HD];

// =========================================================================
// 1) prefix copy
// =========================================================================
__global__ __launch_bounds__(256) void copy_prefix_kernel(
    const float* __restrict__ ki, const float* __restrict__ vi,
    const int* __restrict__ idxp)
{
    const int s  = idxp[0] * HD;
    const int e4 = blockIdx.x * 256 + threadIdx.x;
    const int d4 = e4 & 31;
    const int t  = (e4 >> 5) & (TQ - 1);
    const int b  = e4 >> 16;
    const size_t src = ((size_t)b * TQ + t) * NE + s + (size_t)d4 * 4;
    const size_t dst = ((size_t)b * TKF + t) * HD + (size_t)d4 * 4;
    *(float4*)(g_kf + dst) = *(const float4*)(ki + src);
    *(float4*)(g_vf + dst) = *(const float4*)(vi + src);
}

// =========================================================================
// 2) fused projection GEMM: grid.y = mode (0:q -> g_q, 1:k -> g_kf, 2:v -> g_vf)
// =========================================================================
__global__ __launch_bounds__(256) void proj_kernel(
    const float* __restrict__ X,
    const float* __restrict__ Wq, const float* __restrict__ Wk,
    const float* __restrict__ Wv,
    const float* __restrict__ bq, const float* __restrict__ bk,
    const float* __restrict__ bv)
{
    __shared__ float As[64][17];
    __shared__ float Bs[16][128];
    const int mode = blockIdx.y;
    const float* W    = (mode == 0) ? Wq : (mode == 1) ? Wk : Wv;
    const float* bias = (mode == 0) ? bq : (mode == 1) ? bk : bv;
    float* dst        = (mode == 0) ? g_q : (mode == 1) ? g_kf : g_vf;

    const int t   = threadIdx.x;
    const int bm0 = blockIdx.x * 64;
    const int tr  = t >> 4;
    const int tc  = t & 15;

    ull acc[4][4];
    #pragma unroll
    for (int i = 0; i < 4; i++)
        #pragma unroll
        for (int j = 0; j < 4; j++) acc[i][j] = 0ULL;

    const int ar = t >> 2, ac = (t & 3) * 4;
    const int br = t >> 5, bc = (t & 31) * 4;

    for (int k0 = 0; k0 < NE; k0 += 16) {
        float4 av = *(const float4*)(X + (size_t)(bm0 + ar) * NE + k0 + ac);
        As[ar][ac + 0] = av.x; As[ar][ac + 1] = av.y;
        As[ar][ac + 2] = av.z; As[ar][ac + 3] = av.w;
        *(float4*)(&Bs[br][bc])     = *(const float4*)(W + (size_t)(k0 + br) * HD + bc);
        *(float4*)(&Bs[br + 8][bc]) = *(const float4*)(W + (size_t)(k0 + br + 8) * HD + bc);
        __syncthreads();
        #pragma unroll
        for (int kk = 0; kk < 16; kk++) {
            ull pa[4];
            #pragma unroll
            for (int i = 0; i < 4; i++) pa[i] = dup2(As[tr * 4 + i][kk]);
            ulonglong2 b01 = *(const ulonglong2*)(&Bs[kk][tc * 8]);
            ulonglong2 b23 = *(const ulonglong2*)(&Bs[kk][tc * 8 + 4]);
            #pragma unroll
            for (int i = 0; i < 4; i++) {
                acc[i][0] = ffma2(pa[i], b01.x, acc[i][0]);
                acc[i][1] = ffma2(pa[i], b01.y, acc[i][1]);
                acc[i][2] = ffma2(pa[i], b23.x, acc[i][2]);
                acc[i][3] = ffma2(pa[i], b23.y, acc[i][3]);
            }
        }
        __syncthreads();
    }

    float4 bb0 = *(const float4*)(bias + tc * 8);
    float4 bb1 = *(const float4*)(bias + tc * 8 + 4);
    #pragma unroll
    for (int i = 0; i < 4; i++) {
        int row = bm0 + tr * 4 + i;
        int bi  = row >> 11;
        int tt  = row & (TQ - 1);
        size_t orow = (mode == 0) ? (size_t)row : ((size_t)bi * TKF + TQ + tt);
        float2 a0 = u2f(acc[i][0]), a1 = u2f(acc[i][1]);
        float2 a2 = u2f(acc[i][2]), a3 = u2f(acc[i][3]);
        float4 o0 = make_float4(a0.x + bb0.x, a0.y + bb0.y, a1.x + bb0.z, a1.y + bb0.w);
        float4 o1 = make_float4(a2.x + bb1.x, a2.y + bb1.y, a3.x + bb1.z, a3.y + bb1.w);
        *(float4*)(dst + orow * HD + tc * 8)     = o0;
        *(float4*)(dst + orow * HD + tc * 8 + 4) = o1;
    }
}

// =========================================================================
// 3) causal flash attention, 64 queries/CTA, 64-key tiles (packed FFMA2)
// =========================================================================
#define ATTN_SMEM (3 * 64 * 32 * 16 + 64 * 68 * 4)

__global__ __launch_bounds__(256) void attn_kernel(
    const float* __restrict__ gate, float* __restrict__ out)
{
    extern __shared__ float smem_dyn[];
    float4* Qs = (float4*)smem_dyn;
    float4* Ks = Qs + 64 * 32;
    float4* Vs = Ks + 64 * 32;
    float*  Ss = (float*)(Vs + 64 * 32);

    const int t  = threadIdx.x;
    const int b  = blockIdx.y;
    const int qb = blockIdx.x;
    const int tq = t >> 4;
    const int tk = t & 15;
    const float scale = 0.08838834764831845f;

    const float4* qsrc = (const float4*)(g_q + ((size_t)(b * TQ + qb * 64)) * HD);
    #pragma unroll
    for (int i = 0; i < 8; i++) {
        int idx = t + i * 256; int r = idx >> 5, c = idx & 31;
        Qs[r * 32 + (c ^ ((r >> 2) & 7))] = qsrc[idx];
    }

    float m[4], l[4];
    ull ac2[4][4];
    #pragma unroll
    for (int i = 0; i < 4; i++) {
        m[i] = -1e30f; l[i] = 0.f;
        #pragma unroll
        for (int j = 0; j < 4; j++) ac2[i][j] = 0ULL;
    }

    const int ntiles = qb + 33;
    for (int tile = 0; tile < ntiles; tile++) {
        __syncthreads();
        const float4* ksrc = (const float4*)(g_kf + ((size_t)(b * TKF + tile * 64)) * HD);
        const float4* vsrc = (const float4*)(g_vf + ((size_t)(b * TKF + tile * 64)) * HD);
        #pragma unroll
        for (int i = 0; i < 8; i++) {
            int idx = t + i * 256; int r = idx >> 5, c = idx & 31;
            int sw = r * 32 + (c ^ ((r >> 2) & 7));
            Ks[sw] = ksrc[idx];
            Vs[sw] = vsrc[idx];
        }
        __syncthreads();

        ull s2[4][4];
        #pragma unroll
        for (int i = 0; i < 4; i++)
            #pragma unroll
            for (int j = 0; j < 4; j++) s2[i][j] = 0ULL;

        #pragma unroll 4
        for (int c = 0; c < 32; c++) {
            ulonglong2 a2[4], k2[4];
            #pragma unroll
            for (int i = 0; i < 4; i++)
                a2[i] = *(const ulonglong2*)&Qs[(4 * tq + i) * 32 + (c ^ (tq & 7))];
            #pragma unroll
            for (int j = 0; j < 4; j++)
                k2[j] = *(const ulonglong2*)&Ks[(4 * tk + j) * 32 + (c ^ (tk & 7))];
            #pragma unroll
            for (int i = 0; i < 4; i++)
                #pragma unroll
                for (int j = 0; j < 4; j++)
                    s2[i][j] = ffma2(a2[i].x, k2[j].x,
                               ffma2(a2[i].y, k2[j].y, s2[i][j]));
        }

        float s[4][4];
        const bool lastTile = (tile == ntiles - 1);
        #pragma unroll
        for (int i = 0; i < 4; i++)
            #pragma unroll
            for (int j = 0; j < 4; j++) {
                float2 p = u2f(s2[i][j]);
                s[i][j] = (p.x + p.y) * scale;
                if (lastTile && (4 * tk + j > 4 * tq + i)) s[i][j] = -1e30f;
            }

        float tmax[4];
        #pragma unroll
        for (int i = 0; i < 4; i++)
            tmax[i] = fmaxf(fmaxf(s[i][0], s[i][1]), fmaxf(s[i][2], s[i][3]));
        #pragma unroll
        for (int o = 1; o < 16; o <<= 1)
            #pragma unroll
            for (int i = 0; i < 4; i++)
                tmax[i] = fmaxf(tmax[i], __shfl_xor_sync(0xffffffffu, tmax[i], o));

        float corr[4], rs[4];
        #pragma unroll
        for (int i = 0; i < 4; i++) {
            float mn = fmaxf(m[i], tmax[i]);
            corr[i] = __expf(m[i] - mn);
            m[i] = mn;
            rs[i] = 0.f;
            #pragma unroll
            for (int j = 0; j < 4; j++) {
                s[i][j] = __expf(s[i][j] - mn);
                rs[i] += s[i][j];
            }
        }
        #pragma unroll
        for (int o = 1; o < 16; o <<= 1)
            #pragma unroll
            for (int i = 0; i < 4; i++)
                rs[i] += __shfl_xor_sync(0xffffffffu, rs[i], o);
        #pragma unroll
        for (int i = 0; i < 4; i++) {
            l[i] = l[i] * corr[i] + rs[i];
            ull c2 = dup2(corr[i]);
            #pragma unroll
            for (int j = 0; j < 4; j++) ac2[i][j] = fmul2(ac2[i][j], c2);
            *(float4*)&Ss[(4 * tq + i) * 68 + 4 * tk] =
                make_float4(s[i][0], s[i][1], s[i][2], s[i][3]);
        }
        __syncthreads();

        #pragma unroll 2
        for (int jj = 0; jj < 16; jj++) {
            float4 p[4];
            #pragma unroll
            for (int i = 0; i < 4; i++)
                p[i] = *(const float4*)&Ss[(4 * tq + i) * 68 + jj * 4];
            #pragma unroll
            for (int e = 0; e < 4; e++) {
                int j = jj * 4 + e;
                int key = (j >> 2) & 7;
                ulonglong2 v0 = *(const ulonglong2*)&Vs[j * 32 + (tk ^ key)];
                ulonglong2 v1 = *(const ulonglong2*)&Vs[j * 32 + ((16 + tk) ^ key)];
                #pragma unroll
                for (int i = 0; i < 4; i++) {
                    float pv = (e == 0) ? p[i].x : (e == 1) ? p[i].y
                             : (e == 2) ? p[i].z : p[i].w;
                    ull pv2 = dup2(pv);
                    ac2[i][0] = ffma2(pv2, v0.x, ac2[i][0]);
                    ac2[i][1] = ffma2(pv2, v0.y, ac2[i][1]);
                    ac2[i][2] = ffma2(pv2, v1.x, ac2[i][2]);
                    ac2[i][3] = ffma2(pv2, v1.y, ac2[i][3]);
                }
            }
        }
    }

    const float gv = gate[0];
    #pragma unroll
    for (int i = 0; i < 4; i++) {
        float inv = gv / l[i];
        size_t row = (size_t)(b * TQ + qb * 64 + 4 * tq + i) * HD;
        float2 a0 = u2f(ac2[i][0]), a1 = u2f(ac2[i][1]);
        float2 a2 = u2f(ac2[i][2]), a3 = u2f(ac2[i][3]);
        float4 o0 = make_float4(a0.x * inv, a0.y * inv, a1.x * inv, a1.y * inv);
        float4 o1 = make_float4(a2.x * inv, a2.y * inv, a3.x * inv, a3.y * inv);
        *(float4*)(out + row + 4 * tk)      = o0;
        *(float4*)(out + row + 64 + 4 * tk) = o1;
    }
}

// =========================================================================
// 4) kNN memory attention — VERBATIM the R3-passing scalar version
//    (selection path must stay bit-identical)
// =========================================================================
__global__ __launch_bounds__(256) void mem_kernel(
    const float* __restrict__ mem_keys, const float* __restrict__ mem_vals,
    const float* __restrict__ gate, float* __restrict__ out)
{
    __shared__ float4 Qs[32 * 32];
    __shared__ float4 Ks[64 * 32];

    const int t  = threadIdx.x;
    const int b  = blockIdx.y;
    const int q0 = blockIdx.x * 32;
    const int mq = t >> 3;
    const int g  = t & 7;

    const float4* qsrc = (const float4*)(g_q + ((size_t)(b * TQ + q0)) * HD);
    #pragma unroll
    for (int i = 0; i < 4; i++) {
        int idx = t + i * 256; int r = idx >> 5, c = idx & 31;
        Qs[r * 32 + (c ^ (r & 7))] = qsrc[idx];
    }

    float lv[32]; int li[32];
    #pragma unroll
    for (int i = 0; i < 32; i++) { lv[i] = -1e30f; li[i] = 0; }
    float vmin = -1e30f; int amin = 0;

    const float4* kb = (const float4*)(mem_keys + (size_t)b * NM * HD);

    for (int tile = 0; tile < NM / 64; tile++) {
        __syncthreads();
        #pragma unroll
        for (int i = 0; i < 8; i++) {
            int idx = t + i * 256; int r = idx >> 5, c = idx & 31;
            Ks[r * 32 + (c ^ ((r >> 3) & 7))] = kb[(size_t)tile * 2048 + idx];
        }
        __syncthreads();

        float s[8];
        #pragma unroll
        for (int j = 0; j < 8; j++) s[j] = 0.f;
        #pragma unroll 4
        for (int c = 0; c < 32; c++) {
            float4 a = Qs[mq * 32 + (c ^ (mq & 7))];
            #pragma unroll
            for (int j = 0; j < 8; j++) {
                float4 kv = Ks[(8 * g + j) * 32 + (c ^ g)];
                s[j] = fmaf(a.w, kv.w, fmaf(a.z, kv.z,
                       fmaf(a.y, kv.y, fmaf(a.x, kv.x, s[j]))));
            }
        }

        #pragma unroll
        for (int j = 0; j < 8; j++) {
            if (s[j] > vmin) {
                lv[amin] = s[j]; li[amin] = tile * 64 + 8 * g + j;
                vmin = lv[0]; amin = 0;
                #pragma unroll 8
                for (int p = 1; p < 32; p++)
                    if (lv[p] < vmin) { vmin = lv[p]; amin = p; }
            }
        }
    }

    for (int a = 1; a < 32; a++) {
        float v = lv[a]; int ii = li[a]; int p = a - 1;
        while (p >= 0 && lv[p] < v) { lv[p + 1] = lv[p]; li[p + 1] = li[p]; p--; }
        lv[p + 1] = v; li[p + 1] = ii;
    }

    const int lane = t & 31;
    const float* vb = mem_vals + (size_t)b * NM * HD;
    float accv[16];
    #pragma unroll
    for (int u = 0; u < 16; u++) accv[u] = 0.f;
    float sumw = 0.f, vmax = 0.f;
    int ptr = 0;

    for (int it = 0; it < 32; it++) {
        float bv = (ptr < 32) ? lv[ptr] : -1e30f;
        int   wl = lane;
        #pragma unroll
        for (int o = 1; o < 8; o <<= 1) {
            float ov = __shfl_xor_sync(0xffffffffu, bv, o);
            int   ol = __shfl_xor_sync(0xffffffffu, wl, o);
            if (ov > bv) { bv = ov; wl = ol; }
        }
        int myi  = li[ptr < 32 ? ptr : 31];
        int widx = __shfl_sync(0xffffffffu, myi, wl);
        if (lane == wl) ptr++;
        if (it == 0) vmax = bv;
        float w = __expf((bv - vmax) * 0.03125f);
        sumw += w;
        const float4* vrow = (const float4*)(vb + (size_t)widx * HD) + g * 4;
        #pragma unroll
        for (int u = 0; u < 4; u++) {
            float4 vv = vrow[u];
            accv[4 * u + 0] = fmaf(w, vv.x, accv[4 * u + 0]);
            accv[4 * u + 1] = fmaf(w, vv.y, accv[4 * u + 1]);
            accv[4 * u + 2] = fmaf(w, vv.z, accv[4 * u + 2]);
            accv[4 * u + 3] = fmaf(w, vv.w, accv[4 * u + 3]);
        }
    }

    const float sc = (1.0f - gate[0]) / sumw;
    float* orow = out + ((size_t)(b * TQ + q0 + mq)) * HD + g * 16;
    #pragma unroll
    for (int u = 0; u < 4; u++) {
        float4 o = ((float4*)orow)[u];
        o.x += sc * accv[4 * u + 0];
        o.y += sc * accv[4 * u + 1];
        o.z += sc * accv[4 * u + 2];
        o.w += sc * accv[4 * u + 3];
        ((float4*)orow)[u] = o;
    }
}

// =========================================================================
extern "C" void kernel_launch(void* const* d_in, const int* in_sizes, int n_in,
                              void* d_out, int out_size) {
    const float* x        = (const float*)d_in[0];
    const float* ki       = (const float*)d_in[1];
    const float* vi       = (const float*)d_in[2];
    const float* mem_keys = (const float*)d_in[3];
    const float* mem_vals = (const float*)d_in[4];
    const float* Wq       = (const float*)d_in[5];
    const float* bq       = (const float*)d_in[6];
    const float* Wk       = (const float*)d_in[7];
    const float* bk       = (const float*)d_in[8];
    const float* Wv       = (const float*)d_in[9];
    const float* bv       = (const float*)d_in[10];
    const float* gate     = (const float*)d_in[11];
    const int*   idxp     = (const int*)d_in[12];
    float* out = (float*)d_out;

    cudaFuncSetAttribute(attn_kernel, cudaFuncAttributeMaxDynamicSharedMemorySize,
                         ATTN_SMEM);

    copy_prefix_kernel<<<1024, 256>>>(ki, vi, idxp);
    proj_kernel<<<dim3(128, 3), 256>>>(x, Wq, Wk, Wv, bq, bk, bv);
    attn_kernel<<<dim3(32, 4), 256, ATTN_SMEM>>>(gate, out);
    mem_kernel<<<dim3(64, 4), 256>>>(mem_keys, mem_vals, gate, out);
}

// round 7
// speedup vs baseline: 1.3433x; 1.3074x over previous
#include <cuda_runtime.h>
#include <cstdint>

#define NB   4
#define TQ   2048
#define NE   1024
#define HD   128
#define TKF  4096
#define NM   16384

typedef unsigned long long ull;

// ---------------- packed f32x2 helpers (sm_103a only) ----------------
__device__ __forceinline__ ull dup2(float x) {
    ull r; asm("mov.b64 %0, {%1, %1};" : "=l"(r) : "f"(x)); return r;
}
__device__ __forceinline__ float2 u2f(ull v) {
    float2 r; asm("mov.b64 {%0, %1}, %2;" : "=f"(r.x), "=f"(r.y) : "l"(v)); return r;
}
__device__ __forceinline__ ull ffma2(ull a, ull b, ull c) {
    ull d; asm("fma.rn.f32x2 %0, %1, %2, %3;" : "=l"(d) : "l"(a), "l"(b), "l"(c)); return d;
}
__device__ __forceinline__ ull fmul2(ull a, ull b) {
    ull d; asm("mul.rn.f32x2 %0, %1, %2;" : "=l"(d) : "l"(a), "l"(b)); return d;
}

// ---------------- device scratch ----------------
__device__ float g_q [(size_t)NB * TQ  * HD];
__device__ float g_kf[(size_t)NB * TKF * HD];
__device__ float g_vf[(size_t)NB * TKF * HD];

// =========================================================================
// 1) prefix copy
// =========================================================================
__global__ __launch_bounds__(256) void copy_prefix_kernel(
    const float* __restrict__ ki, const float* __restrict__ vi,
    const int* __restrict__ idxp)
{
    const int s  = idxp[0] * HD;
    const int e4 = blockIdx.x * 256 + threadIdx.x;
    const int d4 = e4 & 31;
    const int t  = (e4 >> 5) & (TQ - 1);
    const int b  = e4 >> 16;
    const size_t src = ((size_t)b * TQ + t) * NE + s + (size_t)d4 * 4;
    const size_t dst = ((size_t)b * TKF + t) * HD + (size_t)d4 * 4;
    *(float4*)(g_kf + dst) = *(const float4*)(ki + src);
    *(float4*)(g_vf + dst) = *(const float4*)(vi + src);
}

// =========================================================================
// 2) fused projection GEMM (packed FFMA2)
// =========================================================================
__global__ __launch_bounds__(256) void proj_kernel(
    const float* __restrict__ X,
    const float* __restrict__ Wq, const float* __restrict__ Wk,
    const float* __restrict__ Wv,
    const float* __restrict__ bq, const float* __restrict__ bk,
    const float* __restrict__ bv)
{
    __shared__ float As[64][17];
    __shared__ float Bs[16][128];
    const int mode = blockIdx.y;
    const float* W    = (mode == 0) ? Wq : (mode == 1) ? Wk : Wv;
    const float* bias = (mode == 0) ? bq : (mode == 1) ? bk : bv;
    float* dst        = (mode == 0) ? g_q : (mode == 1) ? g_kf : g_vf;

    const int t   = threadIdx.x;
    const int bm0 = blockIdx.x * 64;
    const int tr  = t >> 4;
    const int tc  = t & 15;

    ull acc[4][4];
    #pragma unroll
    for (int i = 0; i < 4; i++)
        #pragma unroll
        for (int j = 0; j < 4; j++) acc[i][j] = 0ULL;

    const int ar = t >> 2, ac = (t & 3) * 4;
    const int br = t >> 5, bc = (t & 31) * 4;

    for (int k0 = 0; k0 < NE; k0 += 16) {
        float4 av = *(const float4*)(X + (size_t)(bm0 + ar) * NE + k0 + ac);
        As[ar][ac + 0] = av.x; As[ar][ac + 1] = av.y;
        As[ar][ac + 2] = av.z; As[ar][ac + 3] = av.w;
        *(float4*)(&Bs[br][bc])     = *(const float4*)(W + (size_t)(k0 + br) * HD + bc);
        *(float4*)(&Bs[br + 8][bc]) = *(const float4*)(W + (size_t)(k0 + br + 8) * HD + bc);
        __syncthreads();
        #pragma unroll
        for (int kk = 0; kk < 16; kk++) {
            ull pa[4];
            #pragma unroll
            for (int i = 0; i < 4; i++) pa[i] = dup2(As[tr * 4 + i][kk]);
            ulonglong2 b01 = *(const ulonglong2*)(&Bs[kk][tc * 8]);
            ulonglong2 b23 = *(const ulonglong2*)(&Bs[kk][tc * 8 + 4]);
            #pragma unroll
            for (int i = 0; i < 4; i++) {
                acc[i][0] = ffma2(pa[i], b01.x, acc[i][0]);
                acc[i][1] = ffma2(pa[i], b01.y, acc[i][1]);
                acc[i][2] = ffma2(pa[i], b23.x, acc[i][2]);
                acc[i][3] = ffma2(pa[i], b23.y, acc[i][3]);
            }
        }
        __syncthreads();
    }

    float4 bb0 = *(const float4*)(bias + tc * 8);
    float4 bb1 = *(const float4*)(bias + tc * 8 + 4);
    #pragma unroll
    for (int i = 0; i < 4; i++) {
        int row = bm0 + tr * 4 + i;
        int bi  = row >> 11;
        int tt  = row & (TQ - 1);
        size_t orow = (mode == 0) ? (size_t)row : ((size_t)bi * TKF + TQ + tt);
        float2 a0 = u2f(acc[i][0]), a1 = u2f(acc[i][1]);
        float2 a2 = u2f(acc[i][2]), a3 = u2f(acc[i][3]);
        float4 o0 = make_float4(a0.x + bb0.x, a0.y + bb0.y, a1.x + bb0.z, a1.y + bb0.w);
        float4 o1 = make_float4(a2.x + bb1.x, a2.y + bb1.y, a3.x + bb1.z, a3.y + bb1.w);
        *(float4*)(dst + orow * HD + tc * 8)     = o0;
        *(float4*)(dst + orow * HD + tc * 8 + 4) = o1;
    }
}

// =========================================================================
// 3) causal flash attention (packed FFMA2) — unchanged from passing R6
// =========================================================================
#define ATTN_SMEM (3 * 64 * 32 * 16 + 64 * 68 * 4)

__global__ __launch_bounds__(256) void attn_kernel(
    const float* __restrict__ gate, float* __restrict__ out)
{
    extern __shared__ float smem_dyn[];
    float4* Qs = (float4*)smem_dyn;
    float4* Ks = Qs + 64 * 32;
    float4* Vs = Ks + 64 * 32;
    float*  Ss = (float*)(Vs + 64 * 32);

    const int t  = threadIdx.x;
    const int b  = blockIdx.y;
    const int qb = blockIdx.x;
    const int tq = t >> 4;
    const int tk = t & 15;
    const float scale = 0.08838834764831845f;

    const float4* qsrc = (const float4*)(g_q + ((size_t)(b * TQ + qb * 64)) * HD);
    #pragma unroll
    for (int i = 0; i < 8; i++) {
        int idx = t + i * 256; int r = idx >> 5, c = idx & 31;
        Qs[r * 32 + (c ^ ((r >> 2) & 7))] = qsrc[idx];
    }

    float m[4], l[4];
    ull ac2[4][4];
    #pragma unroll
    for (int i = 0; i < 4; i++) {
        m[i] = -1e30f; l[i] = 0.f;
        #pragma unroll
        for (int j = 0; j < 4; j++) ac2[i][j] = 0ULL;
    }

    const int ntiles = qb + 33;
    for (int tile = 0; tile < ntiles; tile++) {
        __syncthreads();
        const float4* ksrc = (const float4*)(g_kf + ((size_t)(b * TKF + tile * 64)) * HD);
        const float4* vsrc = (const float4*)(g_vf + ((size_t)(b * TKF + tile * 64)) * HD);
        #pragma unroll
        for (int i = 0; i < 8; i++) {
            int idx = t + i * 256; int r = idx >> 5, c = idx & 31;
            int sw = r * 32 + (c ^ ((r >> 2) & 7));
            Ks[sw] = ksrc[idx];
            Vs[sw] = vsrc[idx];
        }
        __syncthreads();

        ull s2[4][4];
        #pragma unroll
        for (int i = 0; i < 4; i++)
            #pragma unroll
            for (int j = 0; j < 4; j++) s2[i][j] = 0ULL;

        #pragma unroll 4
        for (int c = 0; c < 32; c++) {
            ulonglong2 a2[4], k2[4];
            #pragma unroll
            for (int i = 0; i < 4; i++)
                a2[i] = *(const ulonglong2*)&Qs[(4 * tq + i) * 32 + (c ^ (tq & 7))];
            #pragma unroll
            for (int j = 0; j < 4; j++)
                k2[j] = *(const ulonglong2*)&Ks[(4 * tk + j) * 32 + (c ^ (tk & 7))];
            #pragma unroll
            for (int i = 0; i < 4; i++)
                #pragma unroll
                for (int j = 0; j < 4; j++)
                    s2[i][j] = ffma2(a2[i].x, k2[j].x,
                               ffma2(a2[i].y, k2[j].y, s2[i][j]));
        }

        float s[4][4];
        const bool lastTile = (tile == ntiles - 1);
        #pragma unroll
        for (int i = 0; i < 4; i++)
            #pragma unroll
            for (int j = 0; j < 4; j++) {
                float2 p = u2f(s2[i][j]);
                s[i][j] = (p.x + p.y) * scale;
                if (lastTile && (4 * tk + j > 4 * tq + i)) s[i][j] = -1e30f;
            }

        float tmax[4];
        #pragma unroll
        for (int i = 0; i < 4; i++)
            tmax[i] = fmaxf(fmaxf(s[i][0], s[i][1]), fmaxf(s[i][2], s[i][3]));
        #pragma unroll
        for (int o = 1; o < 16; o <<= 1)
            #pragma unroll
            for (int i = 0; i < 4; i++)
                tmax[i] = fmaxf(tmax[i], __shfl_xor_sync(0xffffffffu, tmax[i], o));

        float corr[4], rs[4];
        #pragma unroll
        for (int i = 0; i < 4; i++) {
            float mn = fmaxf(m[i], tmax[i]);
            corr[i] = __expf(m[i] - mn);
            m[i] = mn;
            rs[i] = 0.f;
            #pragma unroll
            for (int j = 0; j < 4; j++) {
                s[i][j] = __expf(s[i][j] - mn);
                rs[i] += s[i][j];
            }
        }
        #pragma unroll
        for (int o = 1; o < 16; o <<= 1)
            #pragma unroll
            for (int i = 0; i < 4; i++)
                rs[i] += __shfl_xor_sync(0xffffffffu, rs[i], o);
        #pragma unroll
        for (int i = 0; i < 4; i++) {
            l[i] = l[i] * corr[i] + rs[i];
            ull c2 = dup2(corr[i]);
            #pragma unroll
            for (int j = 0; j < 4; j++) ac2[i][j] = fmul2(ac2[i][j], c2);
            *(float4*)&Ss[(4 * tq + i) * 68 + 4 * tk] =
                make_float4(s[i][0], s[i][1], s[i][2], s[i][3]);
        }
        __syncthreads();

        #pragma unroll 2
        for (int jj = 0; jj < 16; jj++) {
            float4 p[4];
            #pragma unroll
            for (int i = 0; i < 4; i++)
                p[i] = *(const float4*)&Ss[(4 * tq + i) * 68 + jj * 4];
            #pragma unroll
            for (int e = 0; e < 4; e++) {
                int j = jj * 4 + e;
                int key = (j >> 2) & 7;
                ulonglong2 v0 = *(const ulonglong2*)&Vs[j * 32 + (tk ^ key)];
                ulonglong2 v1 = *(const ulonglong2*)&Vs[j * 32 + ((16 + tk) ^ key)];
                #pragma unroll
                for (int i = 0; i < 4; i++) {
                    float pv = (e == 0) ? p[i].x : (e == 1) ? p[i].y
                             : (e == 2) ? p[i].z : p[i].w;
                    ull pv2 = dup2(pv);
                    ac2[i][0] = ffma2(pv2, v0.x, ac2[i][0]);
                    ac2[i][1] = ffma2(pv2, v0.y, ac2[i][1]);
                    ac2[i][2] = ffma2(pv2, v1.x, ac2[i][2]);
                    ac2[i][3] = ffma2(pv2, v1.y, ac2[i][3]);
                }
            }
        }
    }

    const float gv = gate[0];
    #pragma unroll
    for (int i = 0; i < 4; i++) {
        float inv = gv / l[i];
        size_t row = (size_t)(b * TQ + qb * 64 + 4 * tq + i) * HD;
        float2 a0 = u2f(ac2[i][0]), a1 = u2f(ac2[i][1]);
        float2 a2 = u2f(ac2[i][2]), a3 = u2f(ac2[i][3]);
        float4 o0 = make_float4(a0.x * inv, a0.y * inv, a1.x * inv, a1.y * inv);
        float4 o1 = make_float4(a2.x * inv, a2.y * inv, a3.x * inv, a3.y * inv);
        *(float4*)(out + row + 4 * tk)      = o0;
        *(float4*)(out + row + 64 + 4 * tk) = o1;
    }
}

// =========================================================================
// 4) kNN memory attention v2: scores bit-identical scalar chains;
//    spill-free sorted-register top-32 + provably-safe shared threshold;
//    lists dumped to smem (overlaying Q/K tiles) for the merge.
// =========================================================================
#define MEM_SMEM (64 * 1024)

__global__ __launch_bounds__(256, 2) void mem_kernel(
    const float* __restrict__ mem_keys, const float* __restrict__ mem_vals,
    const float* __restrict__ gate, float* __restrict__ out)
{
    extern __shared__ float msm[];
    float4* Qs = (float4*)msm;                  // [0, 16KB): 32q x 32 float4
    float4* Ks = (float4*)(msm + 4096);         // [16KB, 48KB): 64k x 32 float4
    float*  lv_s = msm;                         // overlay [0, 32KB): 32 x 256
    int*    li_s = (int*)(msm + 8192);          // overlay [32KB, 64KB)

    const int t  = threadIdx.x;
    const int b  = blockIdx.y;
    const int q0 = blockIdx.x * 32;
    const int mq = t >> 3;
    const int g  = t & 7;

    const float4* qsrc = (const float4*)(g_q + ((size_t)(b * TQ + q0)) * HD);
    #pragma unroll
    for (int i = 0; i < 4; i++) {
        int idx = t + i * 256; int r = idx >> 5, c = idx & 31;
        Qs[r * 32 + (c ^ (r & 7))] = qsrc[idx];
    }

    // sorted-descending top-32 in registers (static indexing only)
    float lv[32]; int li[32];
    #pragma unroll
    for (int i = 0; i < 32; i++) { lv[i] = -1e30f; li[i] = 0; }
    float Tsh = -1e30f;   // shared (8-lane group) rejection threshold

    const float4* kb = (const float4*)(mem_keys + (size_t)b * NM * HD);

    for (int tile = 0; tile < NM / 64; tile++) {
        __syncthreads();
        #pragma unroll
        for (int i = 0; i < 8; i++) {
            int idx = t + i * 256; int r = idx >> 5, c = idx & 31;
            Ks[r * 32 + (c ^ ((r >> 3) & 7))] = kb[(size_t)tile * 2048 + idx];
        }
        __syncthreads();

        // ---- scores: EXACT same fmaf chains as the passing kernel ----
        float s[8];
        #pragma unroll
        for (int j = 0; j < 8; j++) s[j] = 0.f;
        #pragma unroll 4
        for (int c = 0; c < 32; c++) {
            float4 a = Qs[mq * 32 + (c ^ (mq & 7))];
            #pragma unroll
            for (int j = 0; j < 8; j++) {
                float4 kv = Ks[(8 * g + j) * 32 + (c ^ g)];
                s[j] = fmaf(a.w, kv.w, fmaf(a.z, kv.z,
                       fmaf(a.y, kv.y, fmaf(a.x, kv.x, s[j]))));
            }
        }

        // ---- selection: sorted-register insert, shared threshold ----
        #pragma unroll
        for (int j = 0; j < 8; j++) {
            float sv = s[j];
            if (sv > fmaxf(Tsh, lv[31])) {
                int kidx = tile * 64 + 8 * g + j;
                bool pp = true;
                #pragma unroll
                for (int p = 31; p >= 1; p--) {
                    bool pr = lv[p - 1] < sv;
                    float nv = pr ? lv[p - 1] : (pp ? sv : lv[p]);
                    int   ni = pr ? li[p - 1] : (pp ? kidx : li[p]);
                    lv[p] = nv; li[p] = ni;
                    pp = pr;
                }
                if (pp) { lv[0] = sv; li[0] = kidx; }
            }
        }
        // refresh shared threshold = max over the query's 8 lanes of list-min.
        // Safe: a candidate below some lane's 32nd-best has >=32 better
        // candidates globally, so it cannot be in the query's top-32.
        {
            float tm = lv[31];
            tm = fmaxf(tm, __shfl_xor_sync(0xffffffffu, tm, 1));
            tm = fmaxf(tm, __shfl_xor_sync(0xffffffffu, tm, 2));
            tm = fmaxf(tm, __shfl_xor_sync(0xffffffffu, tm, 4));
            Tsh = tm;
        }
    }

    // ---- dump sorted lists to smem (tiles are dead now) ----
    __syncthreads();
    #pragma unroll
    for (int p = 0; p < 32; p++) {
        lv_s[p * 256 + t] = lv[p];
        li_s[p * 256 + t] = li[p];
    }
    __syncthreads();

    // ---- 8-lane tournament merge + fused softmax + gather (scalar) ----
    const int lane = t & 31;
    const float* vb = mem_vals + (size_t)b * NM * HD;
    float accv[16];
    #pragma unroll
    for (int u = 0; u < 16; u++) accv[u] = 0.f;
    float sumw = 0.f, vmax = 0.f;
    int ptr = 0;

    for (int it = 0; it < 32; it++) {
        float bv = (ptr < 32) ? lv_s[ptr * 256 + t] : -1e30f;
        int   wl = lane;
        #pragma unroll
        for (int o = 1; o < 8; o <<= 1) {
            float ov = __shfl_xor_sync(0xffffffffu, bv, o);
            int   ol = __shfl_xor_sync(0xffffffffu, wl, o);
            if (ov > bv) { bv = ov; wl = ol; }
        }
        int myi  = li_s[(ptr < 32 ? ptr : 31) * 256 + t];
        int widx = __shfl_sync(0xffffffffu, myi, wl);
        if (lane == wl) ptr++;
        if (it == 0) vmax = bv;
        float w = __expf((bv - vmax) * 0.03125f);   // 1/sqrt(1024)
        sumw += w;
        const float4* vrow = (const float4*)(vb + (size_t)widx * HD) + g * 4;
        #pragma unroll
        for (int u = 0; u < 4; u++) {
            float4 vv = vrow[u];
            accv[4 * u + 0] = fmaf(w, vv.x, accv[4 * u + 0]);
            accv[4 * u + 1] = fmaf(w, vv.y, accv[4 * u + 1]);
            accv[4 * u + 2] = fmaf(w, vv.z, accv[4 * u + 2]);
            accv[4 * u + 3] = fmaf(w, vv.w, accv[4 * u + 3]);
        }
    }

    const float sc = (1.0f - gate[0]) / sumw;
    float* orow = out + ((size_t)(b * TQ + q0 + mq)) * HD + g * 16;
    #pragma unroll
    for (int u = 0; u < 4; u++) {
        float4 o = ((float4*)orow)[u];
        o.x += sc * accv[4 * u + 0];
        o.y += sc * accv[4 * u + 1];
        o.z += sc * accv[4 * u + 2];
        o.w += sc * accv[4 * u + 3];
        ((float4*)orow)[u] = o;
    }
}

// =========================================================================
extern "C" void kernel_launch(void* const* d_in, const int* in_sizes, int n_in,
                              void* d_out, int out_size) {
    const float* x        = (const float*)d_in[0];
    const float* ki       = (const float*)d_in[1];
    const float* vi       = (const float*)d_in[2];
    const float* mem_keys = (const float*)d_in[3];
    const float* mem_vals = (const float*)d_in[4];
    const float* Wq       = (const float*)d_in[5];
    const float* bq       = (const float*)d_in[6];
    const float* Wk       = (const float*)d_in[7];
    const float* bk       = (const float*)d_in[8];
    const float* Wv       = (const float*)d_in[9];
    const float* bv       = (const float*)d_in[10];
    const float* gate     = (const float*)d_in[11];
    const int*   idxp     = (const int*)d_in[12];
    float* out = (float*)d_out;

    cudaFuncSetAttribute(attn_kernel, cudaFuncAttributeMaxDynamicSharedMemorySize,
                         ATTN_SMEM);
    cudaFuncSetAttribute(mem_kernel, cudaFuncAttributeMaxDynamicSharedMemorySize,
                         MEM_SMEM);

    copy_prefix_kernel<<<1024, 256>>>(ki, vi, idxp);
    proj_kernel<<<dim3(128, 3), 256>>>(x, Wq, Wk, Wv, bq, bk, bv);
    attn_kernel<<<dim3(32, 4), 256, ATTN_SMEM>>>(gate, out);
    mem_kernel<<<dim3(64, 4), 256, MEM_SMEM>>>(mem_keys, mem_vals, gate, out);
}

// round 8
// speedup vs baseline: 1.4953x; 1.1132x over previous
#include <cuda_runtime.h>
#include <cstdint>

#define NB   4
#define TQ   2048
#define NE   1024
#define HD   128
#define TKF  4096
#define NM   16384

typedef unsigned long long ull;

// ---------------- packed f32x2 helpers (sm_103a only) ----------------
__device__ __forceinline__ ull dup2(float x) {
    ull r; asm("mov.b64 %0, {%1, %1};" : "=l"(r) : "f"(x)); return r;
}
__device__ __forceinline__ float2 u2f(ull v) {
    float2 r; asm("mov.b64 {%0, %1}, %2;" : "=f"(r.x), "=f"(r.y) : "l"(v)); return r;
}
__device__ __forceinline__ ull ffma2(ull a, ull b, ull c) {
    ull d; asm("fma.rn.f32x2 %0, %1, %2, %3;" : "=l"(d) : "l"(a), "l"(b), "l"(c)); return d;
}
__device__ __forceinline__ ull fmul2(ull a, ull b) {
    ull d; asm("mul.rn.f32x2 %0, %1, %2;" : "=l"(d) : "l"(a), "l"(b)); return d;
}

// ---------------- cp.async helpers ----------------
__device__ __forceinline__ void cp16(uint32_t dst_smem, const void* src) {
    asm volatile("cp.async.ca.shared.global [%0], [%1], 16;"
                 :: "r"(dst_smem), "l"(src));
}
__device__ __forceinline__ void cp_commit() {
    asm volatile("cp.async.commit_group;");
}
__device__ __forceinline__ void cp_wait0() {
    asm volatile("cp.async.wait_group 0;");
}

// ---------------- device scratch ----------------
__device__ float g_q [(size_t)NB * TQ  * HD];
__device__ float g_kf[(size_t)NB * TKF * HD];
__device__ float g_vf[(size_t)NB * TKF * HD];

// =========================================================================
// 1) prefix copy
// =========================================================================
__global__ __launch_bounds__(256) void copy_prefix_kernel(
    const float* __restrict__ ki, const float* __restrict__ vi,
    const int* __restrict__ idxp)
{
    const int s  = idxp[0] * HD;
    const int e4 = blockIdx.x * 256 + threadIdx.x;
    const int d4 = e4 & 31;
    const int t  = (e4 >> 5) & (TQ - 1);
    const int b  = e4 >> 16;
    const size_t src = ((size_t)b * TQ + t) * NE + s + (size_t)d4 * 4;
    const size_t dst = ((size_t)b * TKF + t) * HD + (size_t)d4 * 4;
    *(float4*)(g_kf + dst) = *(const float4*)(ki + src);
    *(float4*)(g_vf + dst) = *(const float4*)(vi + src);
}

// =========================================================================
// 2) fused projection GEMM (packed FFMA2) — unchanged from passing R7
// =========================================================================
__global__ __launch_bounds__(256) void proj_kernel(
    const float* __restrict__ X,
    const float* __restrict__ Wq, const float* __restrict__ Wk,
    const float* __restrict__ Wv,
    const float* __restrict__ bq, const float* __restrict__ bk,
    const float* __restrict__ bv)
{
    __shared__ float As[64][17];
    __shared__ float Bs[16][128];
    const int mode = blockIdx.y;
    const float* W    = (mode == 0) ? Wq : (mode == 1) ? Wk : Wv;
    const float* bias = (mode == 0) ? bq : (mode == 1) ? bk : bv;
    float* dst        = (mode == 0) ? g_q : (mode == 1) ? g_kf : g_vf;

    const int t   = threadIdx.x;
    const int bm0 = blockIdx.x * 64;
    const int tr  = t >> 4;
    const int tc  = t & 15;

    ull acc[4][4];
    #pragma unroll
    for (int i = 0; i < 4; i++)
        #pragma unroll
        for (int j = 0; j < 4; j++) acc[i][j] = 0ULL;

    const int ar = t >> 2, ac = (t & 3) * 4;
    const int br = t >> 5, bc = (t & 31) * 4;

    for (int k0 = 0; k0 < NE; k0 += 16) {
        float4 av = *(const float4*)(X + (size_t)(bm0 + ar) * NE + k0 + ac);
        As[ar][ac + 0] = av.x; As[ar][ac + 1] = av.y;
        As[ar][ac + 2] = av.z; As[ar][ac + 3] = av.w;
        *(float4*)(&Bs[br][bc])     = *(const float4*)(W + (size_t)(k0 + br) * HD + bc);
        *(float4*)(&Bs[br + 8][bc]) = *(const float4*)(W + (size_t)(k0 + br + 8) * HD + bc);
        __syncthreads();
        #pragma unroll
        for (int kk = 0; kk < 16; kk++) {
            ull pa[4];
            #pragma unroll
            for (int i = 0; i < 4; i++) pa[i] = dup2(As[tr * 4 + i][kk]);
            ulonglong2 b01 = *(const ulonglong2*)(&Bs[kk][tc * 8]);
            ulonglong2 b23 = *(const ulonglong2*)(&Bs[kk][tc * 8 + 4]);
            #pragma unroll
            for (int i = 0; i < 4; i++) {
                acc[i][0] = ffma2(pa[i], b01.x, acc[i][0]);
                acc[i][1] = ffma2(pa[i], b01.y, acc[i][1]);
                acc[i][2] = ffma2(pa[i], b23.x, acc[i][2]);
                acc[i][3] = ffma2(pa[i], b23.y, acc[i][3]);
            }
        }
        __syncthreads();
    }

    float4 bb0 = *(const float4*)(bias + tc * 8);
    float4 bb1 = *(const float4*)(bias + tc * 8 + 4);
    #pragma unroll
    for (int i = 0; i < 4; i++) {
        int row = bm0 + tr * 4 + i;
        int bi  = row >> 11;
        int tt  = row & (TQ - 1);
        size_t orow = (mode == 0) ? (size_t)row : ((size_t)bi * TKF + TQ + tt);
        float2 a0 = u2f(acc[i][0]), a1 = u2f(acc[i][1]);
        float2 a2 = u2f(acc[i][2]), a3 = u2f(acc[i][3]);
        float4 o0 = make_float4(a0.x + bb0.x, a0.y + bb0.y, a1.x + bb0.z, a1.y + bb0.w);
        float4 o1 = make_float4(a2.x + bb1.x, a2.y + bb1.y, a3.x + bb1.z, a3.y + bb1.w);
        *(float4*)(dst + orow * HD + tc * 8)     = o0;
        *(float4*)(dst + orow * HD + tc * 8 + 4) = o1;
    }
}

// =========================================================================
// 3) causal flash attention — double-buffered cp.async K/V pipeline.
//    All arithmetic identical to passing R7.
// =========================================================================
// smem: Qs 32KB | Ks[2] 64KB | Vs[2] 64KB | Ss 17408B  = 181248 B
#define ATTN_SMEM (32768 + 65536 + 65536 + 64 * 68 * 4)

__global__ __launch_bounds__(256) void attn_kernel(
    const float* __restrict__ gate, float* __restrict__ out)
{
    extern __shared__ float smem_dyn[];
    float4* Qs  = (float4*)smem_dyn;                 // 64x32 f4
    float4* Ks0 = Qs + 64 * 32;
    float4* Ks1 = Ks0 + 64 * 32;
    float4* Vs0 = Ks1 + 64 * 32;
    float4* Vs1 = Vs0 + 64 * 32;
    float*  Ss  = (float*)(Vs1 + 64 * 32);           // 64x68

    const int t  = threadIdx.x;
    const int b  = blockIdx.y;
    const int qb = blockIdx.x;
    const int tq = t >> 4;
    const int tk = t & 15;
    const float scale = 0.08838834764831845f;

    const float4* qsrc = (const float4*)(g_q + ((size_t)(b * TQ + qb * 64)) * HD);
    #pragma unroll
    for (int i = 0; i < 8; i++) {
        int idx = t + i * 256; int r = idx >> 5, c = idx & 31;
        Qs[r * 32 + (c ^ ((r >> 2) & 7))] = qsrc[idx];
    }

    float m[4], l[4];
    ull ac2[4][4];
    #pragma unroll
    for (int i = 0; i < 4; i++) {
        m[i] = -1e30f; l[i] = 0.f;
        #pragma unroll
        for (int j = 0; j < 4; j++) ac2[i][j] = 0ULL;
    }

    const float4* kbase = (const float4*)(g_kf + ((size_t)b * TKF) * HD);
    const float4* vbase = (const float4*)(g_vf + ((size_t)b * TKF) * HD);
    const int ntiles = qb + 33;

    // prefetch tile 0
    {
        uint32_t kd = (uint32_t)__cvta_generic_to_shared(Ks0);
        uint32_t vd = (uint32_t)__cvta_generic_to_shared(Vs0);
        #pragma unroll
        for (int i = 0; i < 8; i++) {
            int idx = t + i * 256; int r = idx >> 5, c = idx & 31;
            uint32_t off = (uint32_t)(r * 32 + (c ^ ((r >> 2) & 7))) * 16u;
            cp16(kd + off, kbase + idx);
            cp16(vd + off, vbase + idx);
        }
        cp_commit();
    }

    for (int tile = 0; tile < ntiles; tile++) {
        cp_wait0();
        __syncthreads();
        const float4* Ks = (tile & 1) ? Ks1 : Ks0;
        const float4* Vs = (tile & 1) ? Vs1 : Vs0;

        if (tile + 1 < ntiles) {
            float4* Kn = (tile & 1) ? Ks0 : Ks1;
            float4* Vn = (tile & 1) ? Vs0 : Vs1;
            uint32_t kd = (uint32_t)__cvta_generic_to_shared(Kn);
            uint32_t vd = (uint32_t)__cvta_generic_to_shared(Vn);
            const float4* ks = kbase + (size_t)(tile + 1) * 64 * 32;
            const float4* vs = vbase + (size_t)(tile + 1) * 64 * 32;
            #pragma unroll
            for (int i = 0; i < 8; i++) {
                int idx = t + i * 256; int r = idx >> 5, c = idx & 31;
                uint32_t off = (uint32_t)(r * 32 + (c ^ ((r >> 2) & 7))) * 16u;
                cp16(kd + off, ks + idx);
                cp16(vd + off, vs + idx);
            }
            cp_commit();
        }

        ull s2[4][4];
        #pragma unroll
        for (int i = 0; i < 4; i++)
            #pragma unroll
            for (int j = 0; j < 4; j++) s2[i][j] = 0ULL;

        #pragma unroll 4
        for (int c = 0; c < 32; c++) {
            ulonglong2 a2[4], k2[4];
            #pragma unroll
            for (int i = 0; i < 4; i++)
                a2[i] = *(const ulonglong2*)&Qs[(4 * tq + i) * 32 + (c ^ (tq & 7))];
            #pragma unroll
            for (int j = 0; j < 4; j++)
                k2[j] = *(const ulonglong2*)&Ks[(4 * tk + j) * 32 + (c ^ (tk & 7))];
            #pragma unroll
            for (int i = 0; i < 4; i++)
                #pragma unroll
                for (int j = 0; j < 4; j++)
                    s2[i][j] = ffma2(a2[i].x, k2[j].x,
                               ffma2(a2[i].y, k2[j].y, s2[i][j]));
        }

        float s[4][4];
        const bool lastTile = (tile == ntiles - 1);
        #pragma unroll
        for (int i = 0; i < 4; i++)
            #pragma unroll
            for (int j = 0; j < 4; j++) {
                float2 p = u2f(s2[i][j]);
                s[i][j] = (p.x + p.y) * scale;
                if (lastTile && (4 * tk + j > 4 * tq + i)) s[i][j] = -1e30f;
            }

        float tmax[4];
        #pragma unroll
        for (int i = 0; i < 4; i++)
            tmax[i] = fmaxf(fmaxf(s[i][0], s[i][1]), fmaxf(s[i][2], s[i][3]));
        #pragma unroll
        for (int o = 1; o < 16; o <<= 1)
            #pragma unroll
            for (int i = 0; i < 4; i++)
                tmax[i] = fmaxf(tmax[i], __shfl_xor_sync(0xffffffffu, tmax[i], o));

        float corr[4], rs[4];
        #pragma unroll
        for (int i = 0; i < 4; i++) {
            float mn = fmaxf(m[i], tmax[i]);
            corr[i] = __expf(m[i] - mn);
            m[i] = mn;
            rs[i] = 0.f;
            #pragma unroll
            for (int j = 0; j < 4; j++) {
                s[i][j] = __expf(s[i][j] - mn);
                rs[i] += s[i][j];
            }
        }
        #pragma unroll
        for (int o = 1; o < 16; o <<= 1)
            #pragma unroll
            for (int i = 0; i < 4; i++)
                rs[i] += __shfl_xor_sync(0xffffffffu, rs[i], o);
        #pragma unroll
        for (int i = 0; i < 4; i++) {
            l[i] = l[i] * corr[i] + rs[i];
            ull c2 = dup2(corr[i]);
            #pragma unroll
            for (int j = 0; j < 4; j++) ac2[i][j] = fmul2(ac2[i][j], c2);
            *(float4*)&Ss[(4 * tq + i) * 68 + 4 * tk] =
                make_float4(s[i][0], s[i][1], s[i][2], s[i][3]);
        }
        __syncthreads();

        #pragma unroll 2
        for (int jj = 0; jj < 16; jj++) {
            float4 p[4];
            #pragma unroll
            for (int i = 0; i < 4; i++)
                p[i] = *(const float4*)&Ss[(4 * tq + i) * 68 + jj * 4];
            #pragma unroll
            for (int e = 0; e < 4; e++) {
                int j = jj * 4 + e;
                int key = (j >> 2) & 7;
                ulonglong2 v0 = *(const ulonglong2*)&Vs[j * 32 + (tk ^ key)];
                ulonglong2 v1 = *(const ulonglong2*)&Vs[j * 32 + ((16 + tk) ^ key)];
                #pragma unroll
                for (int i = 0; i < 4; i++) {
                    float pv = (e == 0) ? p[i].x : (e == 1) ? p[i].y
                             : (e == 2) ? p[i].z : p[i].w;
                    ull pv2 = dup2(pv);
                    ac2[i][0] = ffma2(pv2, v0.x, ac2[i][0]);
                    ac2[i][1] = ffma2(pv2, v0.y, ac2[i][1]);
                    ac2[i][2] = ffma2(pv2, v1.x, ac2[i][2]);
                    ac2[i][3] = ffma2(pv2, v1.y, ac2[i][3]);
                }
            }
        }
        __syncthreads();
    }

    const float gv = gate[0];
    #pragma unroll
    for (int i = 0; i < 4; i++) {
        float inv = gv / l[i];
        size_t row = (size_t)(b * TQ + qb * 64 + 4 * tq + i) * HD;
        float2 a0 = u2f(ac2[i][0]), a1 = u2f(ac2[i][1]);
        float2 a2 = u2f(ac2[i][2]), a3 = u2f(ac2[i][3]);
        float4 o0 = make_float4(a0.x * inv, a0.y * inv, a1.x * inv, a1.y * inv);
        float4 o1 = make_float4(a2.x * inv, a2.y * inv, a3.x * inv, a3.y * inv);
        *(float4*)(out + row + 4 * tk)      = o0;
        *(float4*)(out + row + 64 + 4 * tk) = o1;
    }
}

// =========================================================================
// 4) kNN memory attention — double-buffered cp.async K pipeline.
//    Score chains + selection byte-identical to passing R7.
// =========================================================================
// smem: Qs 16KB | Ks[2] 64KB = 80KB; lists overlay [0, 64KB)
#define MEM_SMEM (81920)

__global__ __launch_bounds__(256, 2) void mem_kernel(
    const float* __restrict__ mem_keys, const float* __restrict__ mem_vals,
    const float* __restrict__ gate, float* __restrict__ out)
{
    extern __shared__ float msm[];
    float4* Qs  = (float4*)msm;                   // [0, 16KB)
    float4* Ks0 = (float4*)(msm + 4096);          // [16KB, 48KB)
    float4* Ks1 = (float4*)(msm + 12288);         // [48KB, 80KB)
    float*  lv_s = msm;                           // overlay [0, 32KB)
    int*    li_s = (int*)(msm + 8192);            // overlay [32KB, 64KB)

    const int t  = threadIdx.x;
    const int b  = blockIdx.y;
    const int q0 = blockIdx.x * 32;
    const int mq = t >> 3;
    const int g  = t & 7;

    const float4* qsrc = (const float4*)(g_q + ((size_t)(b * TQ + q0)) * HD);
    #pragma unroll
    for (int i = 0; i < 4; i++) {
        int idx = t + i * 256; int r = idx >> 5, c = idx & 31;
        Qs[r * 32 + (c ^ (r & 7))] = qsrc[idx];
    }

    float lv[32]; int li[32];
    #pragma unroll
    for (int i = 0; i < 32; i++) { lv[i] = -1e30f; li[i] = 0; }
    float Tsh = -1e30f;

    const float4* kb = (const float4*)(mem_keys + (size_t)b * NM * HD);

    // prefetch tile 0
    {
        uint32_t kd = (uint32_t)__cvta_generic_to_shared(Ks0);
        #pragma unroll
        for (int i = 0; i < 8; i++) {
            int idx = t + i * 256; int r = idx >> 5, c = idx & 31;
            uint32_t off = (uint32_t)(r * 32 + (c ^ ((r >> 3) & 7))) * 16u;
            cp16(kd + off, kb + idx);
        }
        cp_commit();
    }

    for (int tile = 0; tile < NM / 64; tile++) {
        cp_wait0();
        __syncthreads();
        const float4* Ks = (tile & 1) ? Ks1 : Ks0;

        if (tile + 1 < NM / 64) {
            float4* Kn = (tile & 1) ? Ks0 : Ks1;
            uint32_t kd = (uint32_t)__cvta_generic_to_shared(Kn);
            const float4* ks = kb + (size_t)(tile + 1) * 2048;
            #pragma unroll
            for (int i = 0; i < 8; i++) {
                int idx = t + i * 256; int r = idx >> 5, c = idx & 31;
                uint32_t off = (uint32_t)(r * 32 + (c ^ ((r >> 3) & 7))) * 16u;
                cp16(kd + off, ks + idx);
            }
            cp_commit();
        }

        // ---- scores: EXACT same fmaf chains as passing R7 ----
        float s[8];
        #pragma unroll
        for (int j = 0; j < 8; j++) s[j] = 0.f;
        #pragma unroll 4
        for (int c = 0; c < 32; c++) {
            float4 a = Qs[mq * 32 + (c ^ (mq & 7))];
            #pragma unroll
            for (int j = 0; j < 8; j++) {
                float4 kv = Ks[(8 * g + j) * 32 + (c ^ g)];
                s[j] = fmaf(a.w, kv.w, fmaf(a.z, kv.z,
                       fmaf(a.y, kv.y, fmaf(a.x, kv.x, s[j]))));
            }
        }

        // ---- selection: sorted-register insert + shared threshold ----
        #pragma unroll
        for (int j = 0; j < 8; j++) {
            float sv = s[j];
            if (sv > fmaxf(Tsh, lv[31])) {
                int kidx = tile * 64 + 8 * g + j;
                bool pp = true;
                #pragma unroll
                for (int p = 31; p >= 1; p--) {
                    bool pr = lv[p - 1] < sv;
                    float nv = pr ? lv[p - 1] : (pp ? sv : lv[p]);
                    int   ni = pr ? li[p - 1] : (pp ? kidx : li[p]);
                    lv[p] = nv; li[p] = ni;
                    pp = pr;
                }
                if (pp) { lv[0] = sv; li[0] = kidx; }
            }
        }
        {
            float tm = lv[31];
            tm = fmaxf(tm, __shfl_xor_sync(0xffffffffu, tm, 1));
            tm = fmaxf(tm, __shfl_xor_sync(0xffffffffu, tm, 2));
            tm = fmaxf(tm, __shfl_xor_sync(0xffffffffu, tm, 4));
            Tsh = tm;
        }
        __syncthreads();
    }

    // ---- dump sorted lists to smem (tiles dead) ----
    #pragma unroll
    for (int p = 0; p < 32; p++) {
        lv_s[p * 256 + t] = lv[p];
        li_s[p * 256 + t] = li[p];
    }
    __syncthreads();

    // ---- 8-lane tournament merge + fused softmax + gather ----
    const int lane = t & 31;
    const float* vb = mem_vals + (size_t)b * NM * HD;
    float accv[16];
    #pragma unroll
    for (int u = 0; u < 16; u++) accv[u] = 0.f;
    float sumw = 0.f, vmax = 0.f;
    int ptr = 0;

    for (int it = 0; it < 32; it++) {
        float bv = (ptr < 32) ? lv_s[ptr * 256 + t] : -1e30f;
        int   wl = lane;
        #pragma unroll
        for (int o = 1; o < 8; o <<= 1) {
            float ov = __shfl_xor_sync(0xffffffffu, bv, o);
            int   ol = __shfl_xor_sync(0xffffffffu, wl, o);
            if (ov > bv) { bv = ov; wl = ol; }
        }
        int myi  = li_s[(ptr < 32 ? ptr : 31) * 256 + t];
        int widx = __shfl_sync(0xffffffffu, myi, wl);
        if (lane == wl) ptr++;
        if (it == 0) vmax = bv;
        float w = __expf((bv - vmax) * 0.03125f);   // 1/sqrt(1024)
        sumw += w;
        const float4* vrow = (const float4*)(vb + (size_t)widx * HD) + g * 4;
        #pragma unroll
        for (int u = 0; u < 4; u++) {
            float4 vv = vrow[u];
            accv[4 * u + 0] = fmaf(w, vv.x, accv[4 * u + 0]);
            accv[4 * u + 1] = fmaf(w, vv.y, accv[4 * u + 1]);
            accv[4 * u + 2] = fmaf(w, vv.z, accv[4 * u + 2]);
            accv[4 * u + 3] = fmaf(w, vv.w, accv[4 * u + 3]);
        }
    }

    const float sc = (1.0f - gate[0]) / sumw;
    float* orow = out + ((size_t)(b * TQ + q0 + mq)) * HD + g * 16;
    #pragma unroll
    for (int u = 0; u < 4; u++) {
        float4 o = ((float4*)orow)[u];
        o.x += sc * accv[4 * u + 0];
        o.y += sc * accv[4 * u + 1];
        o.z += sc * accv[4 * u + 2];
        o.w += sc * accv[4 * u + 3];
        ((float4*)orow)[u] = o;
    }
}

// =========================================================================
extern "C" void kernel_launch(void* const* d_in, const int* in_sizes, int n_in,
                              void* d_out, int out_size) {
    const float* x        = (const float*)d_in[0];
    const float* ki       = (const float*)d_in[1];
    const float* vi       = (const float*)d_in[2];
    const float* mem_keys = (const float*)d_in[3];
    const float* mem_vals = (const float*)d_in[4];
    const float* Wq       = (const float*)d_in[5];
    const float* bq       = (const float*)d_in[6];
    const float* Wk       = (const float*)d_in[7];
    const float* bk       = (const float*)d_in[8];
    const float* Wv       = (const float*)d_in[9];
    const float* bv       = (const float*)d_in[10];
    const float* gate     = (const float*)d_in[11];
    const int*   idxp     = (const int*)d_in[12];
    float* out = (float*)d_out;

    cudaFuncSetAttribute(attn_kernel, cudaFuncAttributeMaxDynamicSharedMemorySize,
                         ATTN_SMEM);
    cudaFuncSetAttribute(mem_kernel, cudaFuncAttributeMaxDynamicSharedMemorySize,
                         MEM_SMEM);

    copy_prefix_kernel<<<1024, 256>>>(ki, vi, idxp);
    proj_kernel<<<dim3(128, 3), 256>>>(x, Wq, Wk, Wv, bq, bk, bv);
    attn_kernel<<<dim3(32, 4), 256, ATTN_SMEM>>>(gate, out);
    mem_kernel<<<dim3(64, 4), 256, MEM_SMEM>>>(mem_keys, mem_vals, gate, out);
}

// round 9
// speedup vs baseline: 1.7889x; 1.1963x over previous
#include <cuda_runtime.h>
#include <cstdint>

#define NB   4
#define TQ   2048
#define NE   1024
#define HD   128
#define TKF  4096
#define NM   16384

typedef unsigned long long ull;

// ---------------- packed f32x2 helpers (sm_103a only) ----------------
__device__ __forceinline__ ull dup2(float x) {
    ull r; asm("mov.b64 %0, {%1, %1};" : "=l"(r) : "f"(x)); return r;
}
__device__ __forceinline__ float2 u2f(ull v) {
    float2 r; asm("mov.b64 {%0, %1}, %2;" : "=f"(r.x), "=f"(r.y) : "l"(v)); return r;
}
__device__ __forceinline__ ull ffma2(ull a, ull b, ull c) {
    ull d; asm("fma.rn.f32x2 %0, %1, %2, %3;" : "=l"(d) : "l"(a), "l"(b), "l"(c)); return d;
}
__device__ __forceinline__ ull fmul2(ull a, ull b) {
    ull d; asm("mul.rn.f32x2 %0, %1, %2;" : "=l"(d) : "l"(a), "l"(b)); return d;
}

// ---------------- cp.async helpers ----------------
__device__ __forceinline__ void cp16(uint32_t dst_smem, const void* src) {
    asm volatile("cp.async.ca.shared.global [%0], [%1], 16;"
                 :: "r"(dst_smem), "l"(src));
}
__device__ __forceinline__ void cp_commit() {
    asm volatile("cp.async.commit_group;");
}
__device__ __forceinline__ void cp_wait0() {
    asm volatile("cp.async.wait_group 0;");
}

// ---------------- device scratch ----------------
__device__ float g_q [(size_t)NB * TQ  * HD];
__device__ float g_kf[(size_t)NB * TKF * HD];
__device__ float g_vf[(size_t)NB * TKF * HD];

// =========================================================================
// 1) prefix copy
// =========================================================================
__global__ __launch_bounds__(256) void copy_prefix_kernel(
    const float* __restrict__ ki, const float* __restrict__ vi,
    const int* __restrict__ idxp)
{
    const int s  = idxp[0] * HD;
    const int e4 = blockIdx.x * 256 + threadIdx.x;
    const int d4 = e4 & 31;
    const int t  = (e4 >> 5) & (TQ - 1);
    const int b  = e4 >> 16;
    const size_t src = ((size_t)b * TQ + t) * NE + s + (size_t)d4 * 4;
    const size_t dst = ((size_t)b * TKF + t) * HD + (size_t)d4 * 4;
    *(float4*)(g_kf + dst) = *(const float4*)(ki + src);
    *(float4*)(g_vf + dst) = *(const float4*)(vi + src);
}

// =========================================================================
// 2) fused projection GEMM (packed FFMA2) — unchanged from passing R8
// =========================================================================
__global__ __launch_bounds__(256) void proj_kernel(
    const float* __restrict__ X,
    const float* __restrict__ Wq, const float* __restrict__ Wk,
    const float* __restrict__ Wv,
    const float* __restrict__ bq, const float* __restrict__ bk,
    const float* __restrict__ bv)
{
    __shared__ float As[64][17];
    __shared__ float Bs[16][128];
    const int mode = blockIdx.y;
    const float* W    = (mode == 0) ? Wq : (mode == 1) ? Wk : Wv;
    const float* bias = (mode == 0) ? bq : (mode == 1) ? bk : bv;
    float* dst        = (mode == 0) ? g_q : (mode == 1) ? g_kf : g_vf;

    const int t   = threadIdx.x;
    const int bm0 = blockIdx.x * 64;
    const int tr  = t >> 4;
    const int tc  = t & 15;

    ull acc[4][4];
    #pragma unroll
    for (int i = 0; i < 4; i++)
        #pragma unroll
        for (int j = 0; j < 4; j++) acc[i][j] = 0ULL;

    const int ar = t >> 2, ac = (t & 3) * 4;
    const int br = t >> 5, bc = (t & 31) * 4;

    for (int k0 = 0; k0 < NE; k0 += 16) {
        float4 av = *(const float4*)(X + (size_t)(bm0 + ar) * NE + k0 + ac);
        As[ar][ac + 0] = av.x; As[ar][ac + 1] = av.y;
        As[ar][ac + 2] = av.z; As[ar][ac + 3] = av.w;
        *(float4*)(&Bs[br][bc])     = *(const float4*)(W + (size_t)(k0 + br) * HD + bc);
        *(float4*)(&Bs[br + 8][bc]) = *(const float4*)(W + (size_t)(k0 + br + 8) * HD + bc);
        __syncthreads();
        #pragma unroll
        for (int kk = 0; kk < 16; kk++) {
            ull pa[4];
            #pragma unroll
            for (int i = 0; i < 4; i++) pa[i] = dup2(As[tr * 4 + i][kk]);
            ulonglong2 b01 = *(const ulonglong2*)(&Bs[kk][tc * 8]);
            ulonglong2 b23 = *(const ulonglong2*)(&Bs[kk][tc * 8 + 4]);
            #pragma unroll
            for (int i = 0; i < 4; i++) {
                acc[i][0] = ffma2(pa[i], b01.x, acc[i][0]);
                acc[i][1] = ffma2(pa[i], b01.y, acc[i][1]);
                acc[i][2] = ffma2(pa[i], b23.x, acc[i][2]);
                acc[i][3] = ffma2(pa[i], b23.y, acc[i][3]);
            }
        }
        __syncthreads();
    }

    float4 bb0 = *(const float4*)(bias + tc * 8);
    float4 bb1 = *(const float4*)(bias + tc * 8 + 4);
    #pragma unroll
    for (int i = 0; i < 4; i++) {
        int row = bm0 + tr * 4 + i;
        int bi  = row >> 11;
        int tt  = row & (TQ - 1);
        size_t orow = (mode == 0) ? (size_t)row : ((size_t)bi * TKF + TQ + tt);
        float2 a0 = u2f(acc[i][0]), a1 = u2f(acc[i][1]);
        float2 a2 = u2f(acc[i][2]), a3 = u2f(acc[i][3]);
        float4 o0 = make_float4(a0.x + bb0.x, a0.y + bb0.y, a1.x + bb0.z, a1.y + bb0.w);
        float4 o1 = make_float4(a2.x + bb1.x, a2.y + bb1.y, a3.x + bb1.z, a3.y + bb1.w);
        *(float4*)(dst + orow * HD + tc * 8)     = o0;
        *(float4*)(dst + orow * HD + tc * 8 + 4) = o1;
    }
}

// =========================================================================
// 3) causal flash attention — double-buffered cp.async (unchanged from R8)
// =========================================================================
#define ATTN_SMEM (32768 + 65536 + 65536 + 64 * 68 * 4)

__global__ __launch_bounds__(256) void attn_kernel(
    const float* __restrict__ gate, float* __restrict__ out)
{
    extern __shared__ float smem_dyn[];
    float4* Qs  = (float4*)smem_dyn;
    float4* Ks0 = Qs + 64 * 32;
    float4* Ks1 = Ks0 + 64 * 32;
    float4* Vs0 = Ks1 + 64 * 32;
    float4* Vs1 = Vs0 + 64 * 32;
    float*  Ss  = (float*)(Vs1 + 64 * 32);

    const int t  = threadIdx.x;
    const int b  = blockIdx.y;
    const int qb = blockIdx.x;
    const int tq = t >> 4;
    const int tk = t & 15;
    const float scale = 0.08838834764831845f;

    const float4* qsrc = (const float4*)(g_q + ((size_t)(b * TQ + qb * 64)) * HD);
    #pragma unroll
    for (int i = 0; i < 8; i++) {
        int idx = t + i * 256; int r = idx >> 5, c = idx & 31;
        Qs[r * 32 + (c ^ ((r >> 2) & 7))] = qsrc[idx];
    }

    float m[4], l[4];
    ull ac2[4][4];
    #pragma unroll
    for (int i = 0; i < 4; i++) {
        m[i] = -1e30f; l[i] = 0.f;
        #pragma unroll
        for (int j = 0; j < 4; j++) ac2[i][j] = 0ULL;
    }

    const float4* kbase = (const float4*)(g_kf + ((size_t)b * TKF) * HD);
    const float4* vbase = (const float4*)(g_vf + ((size_t)b * TKF) * HD);
    const int ntiles = qb + 33;

    {
        uint32_t kd = (uint32_t)__cvta_generic_to_shared(Ks0);
        uint32_t vd = (uint32_t)__cvta_generic_to_shared(Vs0);
        #pragma unroll
        for (int i = 0; i < 8; i++) {
            int idx = t + i * 256; int r = idx >> 5, c = idx & 31;
            uint32_t off = (uint32_t)(r * 32 + (c ^ ((r >> 2) & 7))) * 16u;
            cp16(kd + off, kbase + idx);
            cp16(vd + off, vbase + idx);
        }
        cp_commit();
    }

    for (int tile = 0; tile < ntiles; tile++) {
        cp_wait0();
        __syncthreads();
        const float4* Ks = (tile & 1) ? Ks1 : Ks0;
        const float4* Vs = (tile & 1) ? Vs1 : Vs0;

        if (tile + 1 < ntiles) {
            float4* Kn = (tile & 1) ? Ks0 : Ks1;
            float4* Vn = (tile & 1) ? Vs0 : Vs1;
            uint32_t kd = (uint32_t)__cvta_generic_to_shared(Kn);
            uint32_t vd = (uint32_t)__cvta_generic_to_shared(Vn);
            const float4* ks = kbase + (size_t)(tile + 1) * 64 * 32;
            const float4* vs = vbase + (size_t)(tile + 1) * 64 * 32;
            #pragma unroll
            for (int i = 0; i < 8; i++) {
                int idx = t + i * 256; int r = idx >> 5, c = idx & 31;
                uint32_t off = (uint32_t)(r * 32 + (c ^ ((r >> 2) & 7))) * 16u;
                cp16(kd + off, ks + idx);
                cp16(vd + off, vs + idx);
            }
            cp_commit();
        }

        ull s2[4][4];
        #pragma unroll
        for (int i = 0; i < 4; i++)
            #pragma unroll
            for (int j = 0; j < 4; j++) s2[i][j] = 0ULL;

        #pragma unroll 4
        for (int c = 0; c < 32; c++) {
            ulonglong2 a2[4], k2[4];
            #pragma unroll
            for (int i = 0; i < 4; i++)
                a2[i] = *(const ulonglong2*)&Qs[(4 * tq + i) * 32 + (c ^ (tq & 7))];
            #pragma unroll
            for (int j = 0; j < 4; j++)
                k2[j] = *(const ulonglong2*)&Ks[(4 * tk + j) * 32 + (c ^ (tk & 7))];
            #pragma unroll
            for (int i = 0; i < 4; i++)
                #pragma unroll
                for (int j = 0; j < 4; j++)
                    s2[i][j] = ffma2(a2[i].x, k2[j].x,
                               ffma2(a2[i].y, k2[j].y, s2[i][j]));
        }

        float s[4][4];
        const bool lastTile = (tile == ntiles - 1);
        #pragma unroll
        for (int i = 0; i < 4; i++)
            #pragma unroll
            for (int j = 0; j < 4; j++) {
                float2 p = u2f(s2[i][j]);
                s[i][j] = (p.x + p.y) * scale;
                if (lastTile && (4 * tk + j > 4 * tq + i)) s[i][j] = -1e30f;
            }

        float tmax[4];
        #pragma unroll
        for (int i = 0; i < 4; i++)
            tmax[i] = fmaxf(fmaxf(s[i][0], s[i][1]), fmaxf(s[i][2], s[i][3]));
        #pragma unroll
        for (int o = 1; o < 16; o <<= 1)
            #pragma unroll
            for (int i = 0; i < 4; i++)
                tmax[i] = fmaxf(tmax[i], __shfl_xor_sync(0xffffffffu, tmax[i], o));

        float corr[4], rs[4];
        #pragma unroll
        for (int i = 0; i < 4; i++) {
            float mn = fmaxf(m[i], tmax[i]);
            corr[i] = __expf(m[i] - mn);
            m[i] = mn;
            rs[i] = 0.f;
            #pragma unroll
            for (int j = 0; j < 4; j++) {
                s[i][j] = __expf(s[i][j] - mn);
                rs[i] += s[i][j];
            }
        }
        #pragma unroll
        for (int o = 1; o < 16; o <<= 1)
            #pragma unroll
            for (int i = 0; i < 4; i++)
                rs[i] += __shfl_xor_sync(0xffffffffu, rs[i], o);
        #pragma unroll
        for (int i = 0; i < 4; i++) {
            l[i] = l[i] * corr[i] + rs[i];
            ull c2 = dup2(corr[i]);
            #pragma unroll
            for (int j = 0; j < 4; j++) ac2[i][j] = fmul2(ac2[i][j], c2);
            *(float4*)&Ss[(4 * tq + i) * 68 + 4 * tk] =
                make_float4(s[i][0], s[i][1], s[i][2], s[i][3]);
        }
        __syncthreads();

        #pragma unroll 2
        for (int jj = 0; jj < 16; jj++) {
            float4 p[4];
            #pragma unroll
            for (int i = 0; i < 4; i++)
                p[i] = *(const float4*)&Ss[(4 * tq + i) * 68 + jj * 4];
            #pragma unroll
            for (int e = 0; e < 4; e++) {
                int j = jj * 4 + e;
                int key = (j >> 2) & 7;
                ulonglong2 v0 = *(const ulonglong2*)&Vs[j * 32 + (tk ^ key)];
                ulonglong2 v1 = *(const ulonglong2*)&Vs[j * 32 + ((16 + tk) ^ key)];
                #pragma unroll
                for (int i = 0; i < 4; i++) {
                    float pv = (e == 0) ? p[i].x : (e == 1) ? p[i].y
                             : (e == 2) ? p[i].z : p[i].w;
                    ull pv2 = dup2(pv);
                    ac2[i][0] = ffma2(pv2, v0.x, ac2[i][0]);
                    ac2[i][1] = ffma2(pv2, v0.y, ac2[i][1]);
                    ac2[i][2] = ffma2(pv2, v1.x, ac2[i][2]);
                    ac2[i][3] = ffma2(pv2, v1.y, ac2[i][3]);
                }
            }
        }
        __syncthreads();
    }

    const float gv = gate[0];
    #pragma unroll
    for (int i = 0; i < 4; i++) {
        float inv = gv / l[i];
        size_t row = (size_t)(b * TQ + qb * 64 + 4 * tq + i) * HD;
        float2 a0 = u2f(ac2[i][0]), a1 = u2f(ac2[i][1]);
        float2 a2 = u2f(ac2[i][2]), a3 = u2f(ac2[i][3]);
        float4 o0 = make_float4(a0.x * inv, a0.y * inv, a1.x * inv, a1.y * inv);
        float4 o1 = make_float4(a2.x * inv, a2.y * inv, a3.x * inv, a3.y * inv);
        *(float4*)(out + row + 4 * tk)      = o0;
        *(float4*)(out + row + 64 + 4 * tk) = o1;
    }
}

// =========================================================================
// 4) kNN memory attention v3: 2 queries/thread (K register reuse),
//    score chains bit-identical; lane-pair exchange -> 1 top-32 list/thread;
//    exact per construction. 128 threads / 32 queries / CTA.
// =========================================================================
#define MEM_SMEM (81920)

__global__ __launch_bounds__(128, 2) void mem_kernel(
    const float* __restrict__ mem_keys, const float* __restrict__ mem_vals,
    const float* __restrict__ gate, float* __restrict__ out)
{
    extern __shared__ float msm[];
    float4* Qs  = (float4*)msm;                   // [0, 16KB): 32q x 32 f4
    float4* Ks0 = (float4*)(msm + 4096);          // [16KB, 48KB)
    float4* Ks1 = (float4*)(msm + 12288);         // [48KB, 80KB)
    float*  lv_s = msm;                           // overlay [0, 16KB): 32 x 128
    int*    li_s = (int*)(msm + 4096);            // overlay [16KB, 32KB)

    const int t    = threadIdx.x;                 // 0..127
    const int b    = blockIdx.y;
    const int q0   = blockIdx.x * 32;
    const int pair = t >> 3;                      // 0..15: queries (pair, pair+16)
    const int g    = t & 7;                       // 8 keys per lane
    const int h    = g >> 2;                      // 0: owns query A, 1: owns B
    const int lane = t & 31;

    const float4* qsrc = (const float4*)(g_q + ((size_t)(b * TQ + q0)) * HD);
    #pragma unroll
    for (int i = 0; i < 8; i++) {
        int idx = t + i * 128; int r = idx >> 5, c = idx & 31;
        Qs[r * 32 + (c ^ (r & 7))] = qsrc[idx];
    }

    float lv[32]; int li[32];
    #pragma unroll
    for (int i = 0; i < 32; i++) { lv[i] = -1e30f; li[i] = 0; }
    float Tsh = -1e30f;

    const float4* kb = (const float4*)(mem_keys + (size_t)b * NM * HD);

    // prefetch tile 0
    {
        uint32_t kd = (uint32_t)__cvta_generic_to_shared(Ks0);
        #pragma unroll
        for (int i = 0; i < 16; i++) {
            int idx = t + i * 128; int r = idx >> 5, c = idx & 31;
            uint32_t off = (uint32_t)(r * 32 + (c ^ ((r >> 3) & 7))) * 16u;
            cp16(kd + off, kb + idx);
        }
        cp_commit();
    }

    for (int tile = 0; tile < NM / 64; tile++) {
        cp_wait0();
        __syncthreads();
        const float4* Ks = (tile & 1) ? Ks1 : Ks0;

        if (tile + 1 < NM / 64) {
            float4* Kn = (tile & 1) ? Ks0 : Ks1;
            uint32_t kd = (uint32_t)__cvta_generic_to_shared(Kn);
            const float4* ks = kb + (size_t)(tile + 1) * 2048;
            #pragma unroll
            for (int i = 0; i < 16; i++) {
                int idx = t + i * 128; int r = idx >> 5, c = idx & 31;
                uint32_t off = (uint32_t)(r * 32 + (c ^ ((r >> 3) & 7))) * 16u;
                cp16(kd + off, ks + idx);
            }
            cp_commit();
        }

        // ---- scores for BOTH queries; each chain identical to R7/R8 ----
        float sA[8], sB[8];
        #pragma unroll
        for (int j = 0; j < 8; j++) { sA[j] = 0.f; sB[j] = 0.f; }
        #pragma unroll 4
        for (int c = 0; c < 32; c++) {
            float4 aA = Qs[pair * 32 + (c ^ (pair & 7))];
            float4 aB = Qs[(pair + 16) * 32 + (c ^ (pair & 7))];
            #pragma unroll
            for (int j = 0; j < 8; j++) {
                float4 kv = Ks[(8 * g + j) * 32 + (c ^ g)];
                sA[j] = fmaf(aA.w, kv.w, fmaf(aA.z, kv.z,
                        fmaf(aA.y, kv.y, fmaf(aA.x, kv.x, sA[j]))));
                sB[j] = fmaf(aB.w, kv.w, fmaf(aB.z, kv.z,
                        fmaf(aB.y, kv.y, fmaf(aB.x, kv.x, sB[j]))));
            }
        }

        // ---- exchange halves so each lane owns ONE query's candidates ----
        #pragma unroll
        for (int j = 0; j < 8; j++) {
            float rA = __shfl_xor_sync(0xffffffffu, sA[j], 4);
            float rB = __shfl_xor_sync(0xffffffffu, sB[j], 4);
            float c1 = h ? sB[j] : sA[j];
            float c2 = h ? rB : rA;
            int   i1 = tile * 64 + 8 * g + j;
            int   i2 = tile * 64 + 8 * (g ^ 4) + j;
            if (c1 > fmaxf(Tsh, lv[31])) {
                bool pp = true;
                #pragma unroll
                for (int p = 31; p >= 1; p--) {
                    bool pr = lv[p - 1] < c1;
                    float nv = pr ? lv[p - 1] : (pp ? c1 : lv[p]);
                    int   ni = pr ? li[p - 1] : (pp ? i1 : li[p]);
                    lv[p] = nv; li[p] = ni;
                    pp = pr;
                }
                if (pp) { lv[0] = c1; li[0] = i1; }
            }
            if (c2 > fmaxf(Tsh, lv[31])) {
                bool pp = true;
                #pragma unroll
                for (int p = 31; p >= 1; p--) {
                    bool pr = lv[p - 1] < c2;
                    float nv = pr ? lv[p - 1] : (pp ? c2 : lv[p]);
                    int   ni = pr ? li[p - 1] : (pp ? i2 : li[p]);
                    lv[p] = nv; li[p] = ni;
                    pp = pr;
                }
                if (pp) { lv[0] = c2; li[0] = i2; }
            }
        }
        // threshold over the 4 lanes owning the SAME query (masks 1,2 only)
        {
            float tm = lv[31];
            tm = fmaxf(tm, __shfl_xor_sync(0xffffffffu, tm, 1));
            tm = fmaxf(tm, __shfl_xor_sync(0xffffffffu, tm, 2));
            Tsh = tm;
        }
        __syncthreads();
    }

    // ---- dump sorted lists to smem (tiles/Q dead) ----
    #pragma unroll
    for (int p = 0; p < 32; p++) {
        lv_s[p * 128 + t] = lv[p];
        li_s[p * 128 + t] = li[p];
    }
    __syncthreads();

    // ---- two merge passes: pass 0 = query A (lanes h==0), pass 1 = B ----
    const float* vb = mem_vals + (size_t)b * NM * HD;
    const float scg = 1.0f - gate[0];

    #pragma unroll
    for (int pass = 0; pass < 2; pass++) {
        const bool mine = (h == pass);
        float accv[16];
        #pragma unroll
        for (int u = 0; u < 16; u++) accv[u] = 0.f;
        float sumw = 0.f, vmax = 0.f;
        int ptr = 0;

        for (int it = 0; it < 32; it++) {
            float bv = (mine && ptr < 32) ? lv_s[ptr * 128 + t] : -1e30f;
            int   wl = lane;
            #pragma unroll
            for (int o = 1; o < 8; o <<= 1) {
                float ov = __shfl_xor_sync(0xffffffffu, bv, o);
                int   ol = __shfl_xor_sync(0xffffffffu, wl, o);
                if (ov > bv) { bv = ov; wl = ol; }
            }
            int myi  = li_s[(ptr < 32 ? ptr : 31) * 128 + t];
            int widx = __shfl_sync(0xffffffffu, myi, wl);
            if (lane == wl) ptr++;
            if (it == 0) vmax = bv;
            float w = __expf((bv - vmax) * 0.03125f);   // 1/sqrt(1024)
            sumw += w;
            const float4* vrow = (const float4*)(vb + (size_t)widx * HD) + g * 4;
            #pragma unroll
            for (int u = 0; u < 4; u++) {
                float4 vv = vrow[u];
                accv[4 * u + 0] = fmaf(w, vv.x, accv[4 * u + 0]);
                accv[4 * u + 1] = fmaf(w, vv.y, accv[4 * u + 1]);
                accv[4 * u + 2] = fmaf(w, vv.z, accv[4 * u + 2]);
                accv[4 * u + 3] = fmaf(w, vv.w, accv[4 * u + 3]);
            }
        }

        const float sc = scg / sumw;
        const int   qq = q0 + pair + (pass ? 16 : 0);
        float* orow = out + ((size_t)(b * TQ + qq)) * HD + g * 16;
        #pragma unroll
        for (int u = 0; u < 4; u++) {
            float4 o = ((float4*)orow)[u];
            o.x += sc * accv[4 * u + 0];
            o.y += sc * accv[4 * u + 1];
            o.z += sc * accv[4 * u + 2];
            o.w += sc * accv[4 * u + 3];
            ((float4*)orow)[u] = o;
        }
    }
}

// =========================================================================
extern "C" void kernel_launch(void* const* d_in, const int* in_sizes, int n_in,
                              void* d_out, int out_size) {
    const float* x        = (const float*)d_in[0];
    const float* ki       = (const float*)d_in[1];
    const float* vi       = (const float*)d_in[2];
    const float* mem_keys = (const float*)d_in[3];
    const float* mem_vals = (const float*)d_in[4];
    const float* Wq       = (const float*)d_in[5];
    const float* bq       = (const float*)d_in[6];
    const float* Wk       = (const float*)d_in[7];
    const float* bk       = (const float*)d_in[8];
    const float* Wv       = (const float*)d_in[9];
    const float* bv       = (const float*)d_in[10];
    const float* gate     = (const float*)d_in[11];
    const int*   idxp     = (const int*)d_in[12];
    float* out = (float*)d_out;

    cudaFuncSetAttribute(attn_kernel, cudaFuncAttributeMaxDynamicSharedMemorySize,
                         ATTN_SMEM);
    cudaFuncSetAttribute(mem_kernel, cudaFuncAttributeMaxDynamicSharedMemorySize,
                         MEM_SMEM);

    copy_prefix_kernel<<<1024, 256>>>(ki, vi, idxp);
    proj_kernel<<<dim3(128, 3), 256>>>(x, Wq, Wk, Wv, bq, bk, bv);
    attn_kernel<<<dim3(32, 4), 256, ATTN_SMEM>>>(gate, out);
    mem_kernel<<<dim3(64, 4), 128, MEM_SMEM>>>(mem_keys, mem_vals, gate, out);
}